// round 7
// baseline (speedup 1.0000x reference)
#include <cuda_runtime.h>
#include <cuda_bf16.h>
#include <math.h>
#include <stdint.h>

// ---------------- problem constants ----------------
#define BATCH 8
#define SEQ   96
#define PRED  96
#define NVARS 862
#define NMARK 4
#define LTOK  866
#define TTOK  (BATCH*LTOK)   // 6928
#define DM    512
#define DS    16
#define DFF   512
#define RK    32
#define NL    2

// chunked scan
#define NCH   32
#define CHL   28
#define NWARP (2*BATCH*16*NCH)
#define NSTATE ((size_t)NWARP*32*16)

#define CDIV(a,b) (((a)+(b)-1)/(b))

// ================= scratch (static; no allocs) =============================
// units: 4 bytes
constexpr size_t OFF_TOKS = 0;                                   // split [TTOK][96w]
constexpr size_t OFF_DEC  = OFF_TOKS + (size_t)TTOK*96;
constexpr size_t OFF_ENC  = OFF_DEC  + (size_t)TTOK*96;          // fp32
constexpr size_t OFF_ENCS = OFF_ENC  + (size_t)TTOK*DM;          // split
constexpr size_t OFF_RAW  = OFF_ENCS + (size_t)TTOK*DM;
constexpr size_t OFF_RAWS = OFF_RAW  + (size_t)TTOK*DM;
constexpr size_t OFF_XZB  = OFF_RAWS + (size_t)TTOK*DM;          // [T,2048] fp32
constexpr size_t OFF_XCS  = OFF_XZB  + (size_t)TTOK*4*DM;        // split [2][T][512w]
constexpr size_t OFF_DX   = OFF_XCS  + (size_t)2*TTOK*DM;        // [T,2048] (dlt,x)
constexpr size_t OFF_BC   = OFF_DX   + (size_t)TTOK*2048;        // [T,64] (B,C)
constexpr size_t OFF_YPS  = OFF_BC   + (size_t)TTOK*64;          // split [2][T][512w]
constexpr size_t OFF_MO   = OFF_YPS  + (size_t)2*TTOK*DM;        // fp32 [2][T][512]
constexpr size_t OFF_T1   = OFF_MO   + (size_t)2*TTOK*DM;
constexpr size_t OFF_T1S  = OFF_T1   + (size_t)TTOK*DM;
constexpr size_t OFF_T2   = OFF_T1S  + (size_t)TTOK*DM;
constexpr size_t OFF_T2S  = OFF_T2   + (size_t)TTOK*DM;
constexpr size_t OFF_T3   = OFF_T2S  + (size_t)TTOK*DM;
constexpr size_t OFF_WCS  = OFF_T3   + (size_t)TTOK*DM;          // wcomb split [4][544][512w]
constexpr size_t OFF_EMBS = OFF_WCS  + (size_t)4*544*512;
constexpr size_t OFF_INPS = OFF_EMBS + (size_t)512*96;
constexpr size_t OFF_OUTS = OFF_INPS + (size_t)4096*512;
constexpr size_t OFF_F1S  = OFF_OUTS + (size_t)2048*512;
constexpr size_t OFF_F2S  = OFF_F1S  + (size_t)1024*512;
constexpr size_t OFF_GWS  = OFF_F2S  + (size_t)1024*512;
constexpr size_t OFF_PWS  = OFF_GWS  + (size_t)512*512;
constexpr size_t OFF_MEAN = OFF_PWS  + (size_t)96*512;
constexpr size_t OFF_STD  = OFF_MEAN + (size_t)BATCH*NVARS;
constexpr size_t OFF_P    = OFF_STD  + (size_t)BATCH*NVARS;
constexpr size_t OFF_HL   = OFF_P    + NSTATE;
constexpr size_t OFF_HI   = OFF_HL   + NSTATE;
constexpr size_t SCRATCH_FLOATS = OFF_HI + NSTATE;

__device__ float g_scratch[SCRATCH_FLOATS];

// ---- bf16 hi/lo split helpers ----
__device__ __forceinline__ uint32_t pack_bf16(float a, float b) {
    __nv_bfloat162 t = __floats2bfloat162_rn(a, b);
    return *reinterpret_cast<uint32_t*>(&t);
}
// split pair (v0,v1) -> (hi word, lo word)
__device__ __forceinline__ void split2(float v0, float v1,
                                       uint32_t& hi, uint32_t& lo) {
    float h0 = __bfloat162float(__float2bfloat16_rn(v0));
    float h1 = __bfloat162float(__float2bfloat16_rn(v1));
    hi = pack_bf16(h0, h1);
    lo = pack_bf16(v0 - h0, v1 - h1);
}
// split-layout word index for even column c (pairs): row-major rows of N words
__device__ __forceinline__ int sw_idx(int c) {   // c even
    return (c >> 5) * 32 + ((c & 31) >> 1);
}

// ================= bf16-split tensor-core GEMM =============================
// Operands pre-split: A[row][K/32 kt][16 hi | 16 lo] u32 words; W same with
// row stride K words. 3 products: hi*hi + lo*hi + hi*lo.
enum { ACT_NONE = 0, ACT_RELU = 1, ACT_DELTABC = 2, ACT_GATE = 3, ACT_DUP = 4 };
// OUT: 0 = fp32 only, 1 = split only, 2 = both

#define BM 64
#define BN 128
#define LPITCH 36
#define ROWB 144
#define A_TILE_W (64*LPITCH)
#define B_TILE_W (128*LPITCH)
#define STAGE_W  (A_TILE_W + B_TILE_W)      // 6912 words
#define SMEM_GEMM (2*STAGE_W*4)             // 55296 bytes

__device__ __forceinline__ uint32_t smem_u32(const void* p) {
    uint32_t a;
    asm("{ .reg .u64 t; cvta.to.shared.u64 t, %1; cvt.u32.u64 %0, t; }"
        : "=r"(a) : "l"(p));
    return a;
}

#define LDSM_X4(r0,r1,r2,r3,addr) \
    asm volatile("ldmatrix.sync.aligned.m8n8.x4.shared.b16 {%0,%1,%2,%3}, [%4];" \
        : "=r"(r0),"=r"(r1),"=r"(r2),"=r"(r3) : "r"(addr))

#define MMA_BF16(d,a,b0,b1) \
    asm volatile("mma.sync.aligned.m16n8k16.row.col.f32.bf16.bf16.f32 " \
        "{%0,%1,%2,%3}, {%4,%5,%6,%7}, {%8,%9}, {%0,%1,%2,%3};" \
        : "+f"((d)[0]),"+f"((d)[1]),"+f"((d)[2]),"+f"((d)[3]) \
        : "r"((a)[0]),"r"((a)[1]),"r"((a)[2]),"r"((a)[3]), "r"(b0),"r"(b1))

template <int ACT, int OUT>
__global__ void __launch_bounds__(256, 2)
mma_gemm(const uint32_t* __restrict__ A, int ldaw,
         const uint32_t* __restrict__ W,
         const float* __restrict__ bias,
         float* __restrict__ C, int ldc,
         uint32_t* __restrict__ Cs,
         int M, int N, int K,
         const float* __restrict__ e1, const float* __restrict__ e2,
         uint32_t* __restrict__ Cs2,
         size_t zsA, size_t zsW, size_t zsC, size_t zsBias)
{
    extern __shared__ char smem[];
    uint32_t* sm = reinterpret_cast<uint32_t*>(smem);
    const uint32_t sbase = smem_u32(smem);
    const int tid  = threadIdx.x;
    const int lane = tid & 31;
    const int wid  = tid >> 5;
    const int warp_m = wid & 1;
    const int warp_n = wid >> 1;
    const int bm = blockIdx.y * BM, bn = blockIdx.x * BN;

    A += blockIdx.z * zsA;
    W += blockIdx.z * zsW;
    if (C) C += blockIdx.z * zsC;
    if (bias) bias += blockIdx.z * zsBias;

    const int q4  = tid & 7;            // uint4 index within 32-word row chunk
    const int r0g = tid >> 3;           // base row (0..31)

    uint4 aU[2], bU[4];
    const uint4 Z4 = make_uint4(0u, 0u, 0u, 0u);

    auto load_global = [&](int kt) {
#pragma unroll
        for (int i = 0; i < 2; i++) {
            int gr = bm + r0g + i * 32;
            aU[i] = (gr < M)
                ? *reinterpret_cast<const uint4*>(A + (size_t)gr * ldaw + kt * 32 + q4 * 4)
                : Z4;
        }
#pragma unroll
        for (int i = 0; i < 4; i++) {
            int gn = bn + r0g + i * 32;
            bU[i] = (gn < N)
                ? *reinterpret_cast<const uint4*>(W + (size_t)gn * K + kt * 32 + q4 * 4)
                : Z4;
        }
    };

    auto store_stage = [&](int s) {
        uint32_t* sa = sm + s * STAGE_W;
        uint32_t* sb = sa + A_TILE_W;
#pragma unroll
        for (int i = 0; i < 2; i++)
            *reinterpret_cast<uint4*>(sa + (r0g + i * 32) * LPITCH + q4 * 4) = aU[i];
#pragma unroll
        for (int i = 0; i < 4; i++)
            *reinterpret_cast<uint4*>(sb + (r0g + i * 32) * LPITCH + q4 * 4) = bU[i];
    };

    const uint32_t a_off = (uint32_t)(warp_m * 32 + (lane & 15)) * ROWB + ((lane >> 4) * 16);
    const uint32_t b_off = (uint32_t)(warp_n * 32 + ((lane >> 4) & 1) * 8 + (lane & 7)) * ROWB
                         + (((lane >> 3) & 1) * 16);
    const uint32_t Bsm_off = A_TILE_W * 4;

    float acc[2][4][4];
#pragma unroll
    for (int i = 0; i < 2; i++)
#pragma unroll
        for (int j = 0; j < 4; j++)
#pragma unroll
            for (int e = 0; e < 4; e++) acc[i][j][e] = 0.f;

    const int KT = K / 32;
    load_global(0);
    store_stage(0);
    __syncthreads();

    for (int kt = 0; kt < KT; kt++) {
        if (kt + 1 < KT) load_global(kt + 1);
        const uint32_t Ab = sbase + (kt & 1) * (STAGE_W * 4);
        const uint32_t Bb = Ab + Bsm_off;
#pragma unroll
        for (int ks = 0; ks < 6; ks++) {
            const int kk = ks & 1;
            const int segA = (ks == 2 || ks == 3) ? 1 : 0;
            const int segB = (ks >= 4) ? 1 : 0;
            const uint32_t ao = Ab + a_off + segA * 64 + kk * 32;
            const uint32_t bo = Bb + b_off + segB * 64 + kk * 32;
            uint32_t a[2][4];
#pragma unroll
            for (int mt = 0; mt < 2; mt++)
                LDSM_X4(a[mt][0], a[mt][1], a[mt][2], a[mt][3], ao + mt * 16 * ROWB);
            uint32_t b[2][4];
#pragma unroll
            for (int p = 0; p < 2; p++)
                LDSM_X4(b[p][0], b[p][1], b[p][2], b[p][3], bo + p * 16 * ROWB);
#pragma unroll
            for (int mt = 0; mt < 2; mt++) {
                MMA_BF16(acc[mt][0], a[mt], b[0][0], b[0][1]);
                MMA_BF16(acc[mt][1], a[mt], b[0][2], b[0][3]);
                MMA_BF16(acc[mt][2], a[mt], b[1][0], b[1][1]);
                MMA_BF16(acc[mt][3], a[mt], b[1][2], b[1][3]);
            }
        }
        if (kt + 1 < KT) store_stage((kt + 1) & 1);
        __syncthreads();
    }

    // ---- epilogue ----
    const int er = bm + warp_m * 32 + (lane >> 2);
    const int ec = bn + warp_n * 32 + (lane & 3) * 2;
#pragma unroll
    for (int mt = 0; mt < 2; mt++) {
#pragma unroll
        for (int nt = 0; nt < 4; nt++) {
            int gc = ec + nt * 8;
            if (gc >= N) continue;
            float b0 = 0.f, b1 = 0.f;
            if (bias) {
                if (ACT == ACT_DELTABC) {
                    if (gc < 512)     b0 = bias[gc];
                    if (gc + 1 < 512) b1 = bias[gc + 1];
                } else {
                    b0 = bias[gc]; b1 = bias[gc + 1];
                }
            }
#pragma unroll
            for (int h = 0; h < 2; h++) {
                int gr = er + mt * 16 + h * 8;
                if (gr >= M) continue;
                float v0 = acc[mt][nt][h * 2 + 0];
                float v1 = acc[mt][nt][h * 2 + 1];
                if (ACT == ACT_DELTABC) {
                    float* bco = const_cast<float*>(e1) + blockIdx.z * 32;
                    if (gc < 512) {
                        v0 += b0; v1 += b1;
                        v0 = fmaxf(v0, 0.f) + log1pf(__expf(-fabsf(v0)));
                        v1 = fmaxf(v1, 0.f) + log1pf(__expf(-fabsf(v1)));
                        C[(size_t)gr * 2048 + 2 * gc]     = v0;
                        C[(size_t)gr * 2048 + 2 * gc + 2] = v1;
                    } else if (gc < 528) {
                        int s = gc - 512;
                        bco[(size_t)gr * 64 + 2 * s]     = v0;
                        bco[(size_t)gr * 64 + 2 * s + 2] = v1;
                    } else if (gc < 544) {
                        int s = gc - 528;
                        bco[(size_t)gr * 64 + 2 * s + 1] = v0;
                        bco[(size_t)gr * 64 + 2 * s + 3] = v1;
                    }
                    continue;
                }
                v0 += b0; v1 += b1;
                if (ACT == ACT_RELU) { v0 = fmaxf(v0, 0.f); v1 = fmaxf(v1, 0.f); }
                if (ACT == ACT_GATE) {
                    size_t ix = (size_t)gr * ldc + gc;
                    float s0 = 1.f / (1.f + __expf(-v0));
                    float s1 = 1.f / (1.f + __expf(-v1));
                    v0 = e1[ix] + s0 * e2[ix];
                    v1 = e1[ix + 1] + s1 * e2[ix + 1];
                }
                if (OUT == 0 || OUT == 2)
                    *reinterpret_cast<float2*>(&C[(size_t)gr * ldc + gc]) =
                        make_float2(v0, v1);
                if (OUT >= 1) {
                    uint32_t hi, lo;
                    split2(v0, v1, hi, lo);
                    size_t o = (size_t)gr * N + sw_idx(gc);
                    Cs[o] = hi; Cs[o + 16] = lo;
                }
                if (ACT == ACT_DUP) {
                    size_t ix = (size_t)gr * ldc + gc;
                    *reinterpret_cast<float2*>(const_cast<float*>(&e2[ix])) =
                        make_float2(v0, v1);
                    uint32_t hi, lo;
                    split2(v0, v1, hi, lo);
                    size_t o = (size_t)gr * N + sw_idx(gc);
                    Cs2[o] = hi; Cs2[o + 16] = lo;
                }
            }
        }
    }
}

// ================= weight split kernel =====================================
__global__ void wsplit_kernel(const float* __restrict__ src,
                              uint32_t* __restrict__ dst, int rows, int K)
{
    int idx = blockIdx.x * blockDim.x + threadIdx.x;
    int K2 = K >> 1;
    if (idx >= rows * K2) return;
    int row = idx / K2, j = idx - row * K2;
    float v0 = src[(size_t)row * K + 2 * j];
    float v1 = src[(size_t)row * K + 2 * j + 1];
    uint32_t hi, lo;
    split2(v0, v1, hi, lo);
    size_t o = (size_t)row * K + (j >> 4) * 32 + (j & 15);
    dst[o] = hi; dst[o + 16] = lo;
}

// ================= small kernels ==========================================
__global__ void stats_kernel(const float* __restrict__ x_enc,
                             float* __restrict__ means, float* __restrict__ stds)
{
    int idx = blockIdx.x * blockDim.x + threadIdx.x;
    if (idx >= BATCH * NVARS) return;
    int b = idx / NVARS, n = idx - b * NVARS;
    float s = 0.f, sq = 0.f;
    for (int t = 0; t < SEQ; t++) {
        float v = x_enc[((size_t)b * SEQ + t) * NVARS + n];
        s += v; sq += v * v;
    }
    float m = s * (1.f / SEQ);
    float var = sq * (1.f / SEQ) - m * m;
    means[idx] = m;
    stds[idx] = sqrtf(var + 1e-5f);
}

// tokens direct to split format: [t][96 words]
__global__ void tok_kernel(const float* __restrict__ x_enc,
                           const float* __restrict__ x_mark,
                           const float* __restrict__ means,
                           const float* __restrict__ stds,
                           uint32_t* __restrict__ tok_s)
{
    int idx = blockIdx.x * blockDim.x + threadIdx.x;
    if (idx >= TTOK * 48) return;
    int j = idx % 48;
    int t = idx / 48;
    int b = t / LTOK, v = t - b * LTOK;
    int s0 = 2 * j, s1 = 2 * j + 1;
    float val0, val1;
    if (v < NVARS) {
        float m = means[b * NVARS + v], sd = stds[b * NVARS + v];
        val0 = (x_enc[((size_t)b * SEQ + s0) * NVARS + v] - m) / sd;
        val1 = (x_enc[((size_t)b * SEQ + s1) * NVARS + v] - m) / sd;
    } else {
        val0 = x_mark[((size_t)b * SEQ + s0) * NMARK + (v - NVARS)];
        val1 = x_mark[((size_t)b * SEQ + s1) * NMARK + (v - NVARS)];
    }
    uint32_t hi, lo;
    split2(val0, val1, hi, lo);
    size_t o = (size_t)t * 96 + (j >> 4) * 32 + (j & 15);
    tok_s[o] = hi; tok_s[o + 16] = lo;
}

// W_comb split: [w][n][512 words]
__global__ void wcomb_kernel(const float* __restrict__ dtw,
                             const float* __restrict__ xpw,
                             uint32_t* __restrict__ wcs)
{
    int idx = blockIdx.x * blockDim.x + threadIdx.x;
    if (idx >= 4 * 544 * 256) return;
    int w = idx / (544 * 256);
    int rem = idx - w * 544 * 256;
    int n = rem >> 8;
    int k2 = rem & 255;
    int k = 2 * k2;
    float v0, v1;
    if (n < 512) {
        const float* dr = dtw + ((size_t)w * 512 + n) * 32;
        const float* xr = xpw + (size_t)w * 64 * 512 + k;
        v0 = 0.f; v1 = 0.f;
#pragma unroll
        for (int r = 0; r < 32; r++) {
            float dv = dr[r];
            v0 = fmaf(dv, xr[(size_t)r * 512], v0);
            v1 = fmaf(dv, xr[(size_t)r * 512 + 1], v1);
        }
    } else {
        const float* xr = xpw + (size_t)w * 64 * 512 + (size_t)(32 + n - 512) * 512;
        v0 = xr[k]; v1 = xr[k + 1];
    }
    uint32_t hi, lo;
    split2(v0, v1, hi, lo);
    size_t o = ((size_t)w * 544 + n) * 512 + (k2 >> 4) * 32 + (k2 & 15);
    wcs[o] = hi; wcs[o + 16] = lo;
}

// depthwise conv(2) + SiLU, both dirs; writes dx x-slots + xc split
__global__ void conv_silu_kernel(const float* __restrict__ xzB,
                                 const float* __restrict__ cw,
                                 const float* __restrict__ cb,
                                 uint32_t* __restrict__ xcs,   // [2][T][512w]
                                 float* __restrict__ dx)
{
    int idx = blockIdx.x * blockDim.x + threadIdx.x;
    const int n = TTOK * 256;
    if (idx >= 2 * n) return;
    int dir = idx >= n;
    int r = idx - dir * n;
    int d2 = r & 255;
    int t = r >> 8;
    int d = 2 * d2;
    int b = t / LTOK, l = t - b * LTOK;
    const float* base = xzB + (size_t)dir * 1024;
    float2 cur = *reinterpret_cast<const float2*>(base + (size_t)t * 2048 + d);
    int ln = dir ? (l + 1) : (l - 1);
    float2 nbv = make_float2(0.f, 0.f);
    if (ln >= 0 && ln < LTOK)
        nbv = *reinterpret_cast<const float2*>(base + (size_t)(t + (dir ? 1 : -1)) * 2048 + d);
    float4 wv = *reinterpret_cast<const float4*>(cw + (size_t)dir * 1024 + 2 * d);
    float2 cbv = *reinterpret_cast<const float2*>(cb + (size_t)dir * 512 + d);
    float v0 = wv.x * nbv.x + wv.y * cur.x + cbv.x;
    float v1 = wv.z * nbv.y + wv.w * cur.y + cbv.y;
    float o0 = v0 / (1.f + __expf(-v0));
    float o1 = v1 / (1.f + __expf(-v1));
    dx[(size_t)t * 2048 + dir * 1024 + 2 * d + 1] = o0;
    dx[(size_t)t * 2048 + dir * 1024 + 2 * d + 3] = o1;
    uint32_t hi, lo;
    split2(o0, o1, hi, lo);
    size_t o = ((size_t)dir * TTOK + t) * 512 + (d2 >> 4) * 32 + (d2 & 15);
    xcs[o] = hi; xcs[o + 16] = lo;
}

// ---------------- chunked selective scan -----------------------------------
__global__ void __launch_bounds__(256)
scan_p1(const float* __restrict__ dx, const float* __restrict__ bcb,
        const float* __restrict__ A_log_l,
        float* __restrict__ P, float* __restrict__ H)
{
    int w = blockIdx.x * 8 + (threadIdx.x >> 5);
    int lane = threadIdx.x & 31;
    int ch = w & 31;
    int dblk = (w >> 5) & 15;
    int b = (w >> 9) & 7;
    int dir = w >> 12;
    int d = dblk * 32 + lane;

    float a[DS];
    bool structured = true;
#pragma unroll
    for (int s = 0; s < DS; s++) {
        a[s] = -__expf(A_log_l[((size_t)dir * DM + d) * DS + s]) * 1.44269504f;
        structured = structured &&
            (fabsf(a[s] - a[0] * (s + 1)) <= 1e-4f * fabsf(a[0] * (s + 1)));
    }

    float h[DS], Pr[DS];
#pragma unroll
    for (int s = 0; s < DS; s++) { h[s] = 0.f; Pr[s] = 1.f; }

    int i0 = ch * CHL;
    int nn = LTOK - i0; if (nn > CHL) nn = CHL; if (nn < 0) nn = 0;
    int l0 = dir ? (LTOK - 1 - i0) : i0;
    long t0 = (long)b * LTOK + l0;
    long stp = dir ? -1 : 1;
    const float2* dxp = (const float2*)dx + t0 * 1024 + dir * 512 + d;
    const float2* bp  = (const float2*)bcb + t0 * 32 + dir * 16;
    long sdx = stp * 1024, sbc = stp * 32;

    if (structured) {
        const float a0 = a[0];
        for (int i = 0; i < nn; i++) {
            float2 dv = *dxp;
            float u = dv.x * dv.y;
            float q = exp2f(dv.x * a0);
            float dA = 1.f;
#pragma unroll
            for (int s = 0; s < DS; s++) {
                dA *= q;
                float2 bcv = bp[s];
                Pr[s] *= dA;
                h[s] = fmaf(dA, h[s], bcv.x * u);
            }
            dxp += sdx; bp += sbc;
        }
    } else {
        for (int i = 0; i < nn; i++) {
            float2 dv = *dxp;
            float u = dv.x * dv.y;
#pragma unroll
            for (int s = 0; s < DS; s++) {
                float2 bcv = bp[s];
                float dA = exp2f(dv.x * a[s]);
                Pr[s] *= dA;
                h[s] = fmaf(dA, h[s], bcv.x * u);
            }
            dxp += sdx; bp += sbc;
        }
    }
    float* Po = P + ((size_t)w * 32 + lane) * 16;
    float* Ho = H + ((size_t)w * 32 + lane) * 16;
#pragma unroll
    for (int s = 0; s < DS; s++) { Po[s] = Pr[s]; Ho[s] = h[s]; }
}

__global__ void scan_comb(const float* __restrict__ P,
                          const float* __restrict__ Hl,
                          float* __restrict__ Hin)
{
    int idx = blockIdx.x * blockDim.x + threadIdx.x;
    if (idx >= 2 * BATCH * DM * 16) return;
    int s = idx & 15;
    int lane = (idx >> 4) & 31;
    int dblk = (idx >> 9) & 15;
    int b = (idx >> 13) & 7;
    int dir = idx >> 16;
    size_t w0 = (size_t)dir * 4096 + (size_t)b * 512 + (size_t)dblk * 32;
    float h = 0.f;
#pragma unroll
    for (int ch = 0; ch < NCH; ch++) {
        size_t o = ((w0 + ch) * 32 + lane) * 16 + s;
        Hin[o] = h;
        h = P[o] * h + Hl[o];
    }
}

// Pass 2: outputs yp in split format (consumed only by out-proj GEMM)
__global__ void __launch_bounds__(256)
scan_p2(const float* __restrict__ dx, const float* __restrict__ bcb,
        const float* __restrict__ xzB,
        const float* __restrict__ A_log_l,
        const float* __restrict__ Dp_l,
        const float* __restrict__ Hin,
        uint32_t* __restrict__ yps)       // [2][T][512w]
{
    int w = blockIdx.x * 8 + (threadIdx.x >> 5);
    int lane = threadIdx.x & 31;
    int ch = w & 31;
    int dblk = (w >> 5) & 15;
    int b = (w >> 9) & 7;
    int dir = w >> 12;
    int d = dblk * 32 + lane;

    float a[DS];
    bool structured = true;
#pragma unroll
    for (int s = 0; s < DS; s++) {
        a[s] = -__expf(A_log_l[((size_t)dir * DM + d) * DS + s]) * 1.44269504f;
        structured = structured &&
            (fabsf(a[s] - a[0] * (s + 1)) <= 1e-4f * fabsf(a[0] * (s + 1)));
    }
    float Dv = Dp_l[dir * DM + d];

    float h[DS];
    const float* Hi = Hin + ((size_t)w * 32 + lane) * 16;
#pragma unroll
    for (int s = 0; s < DS; s++) h[s] = Hi[s];

    int i0 = ch * CHL;
    int nn = LTOK - i0; if (nn > CHL) nn = CHL; if (nn < 0) nn = 0;
    int l0 = dir ? (LTOK - 1 - i0) : i0;
    long t0 = (long)b * LTOK + l0;
    long stp = dir ? -1 : 1;
    const float2* dxp = (const float2*)dx + t0 * 1024 + dir * 512 + d;
    const float2* bp  = (const float2*)bcb + t0 * 32 + dir * 16;
    const float*  zp  = xzB + t0 * 2048 + dir * 1024 + 512 + d;
    uint32_t* ys = yps + ((size_t)dir * TTOK) * 512 + t0 * 512 + dblk * 32 + (lane >> 1);
    long sdx = stp * 1024, sbc = stp * 32, sz = stp * 2048, sy = stp * 512;
    const float a0 = a[0];

    for (int i = 0; i < nn; i++) {
        float2 dv = *dxp;
        float u = dv.x * dv.y;
        float y0 = 0.f, y1 = 0.f, y2 = 0.f, y3 = 0.f;
        if (structured) {
            float q = exp2f(dv.x * a0);
            float dA = 1.f;
#pragma unroll
            for (int s = 0; s < DS; s++) {
                dA *= q;
                float2 bcv = bp[s];
                h[s] = fmaf(dA, h[s], bcv.x * u);
                float t = h[s] * bcv.y;
                if ((s & 3) == 0) y0 += t;
                else if ((s & 3) == 1) y1 += t;
                else if ((s & 3) == 2) y2 += t;
                else y3 += t;
            }
        } else {
#pragma unroll
            for (int s = 0; s < DS; s++) {
                float2 bcv = bp[s];
                float dA = exp2f(dv.x * a[s]);
                h[s] = fmaf(dA, h[s], bcv.x * u);
                float t = h[s] * bcv.y;
                if ((s & 3) == 0) y0 += t;
                else if ((s & 3) == 1) y1 += t;
                else if ((s & 3) == 2) y2 += t;
                else y3 += t;
            }
        }
        float y = (y0 + y1) + (y2 + y3);
        float z = *zp;
        float szl = z / (1.f + __expf(-z));
        float yv = (y + Dv * dv.y) * szl;
        float yn = __shfl_down_sync(0xffffffffu, yv, 1);
        if (!(lane & 1)) {
            uint32_t hi, lo;
            split2(yv, yn, hi, lo);
            ys[0] = hi; ys[16] = lo;
        }
        dxp += sdx; bp += sbc; zp += sz; ys += sy;
    }
}

// LayerNorm (float2 lanes) with optional split output
__global__ void ln_kernel(const float* __restrict__ i1,
                          const float* __restrict__ i2,
                          const float* __restrict__ i3,
                          const float* __restrict__ g,
                          const float* __restrict__ bta,
                          float* __restrict__ out,
                          uint32_t* __restrict__ out_s)
{
    int row = blockIdx.x * (blockDim.x >> 5) + (threadIdx.x >> 5);
    int lane = threadIdx.x & 31;
    if (row >= TTOK) return;
    const float2* p1 = reinterpret_cast<const float2*>(i1 + (size_t)row * DM);
    const float2* p2 = i2 ? reinterpret_cast<const float2*>(i2 + (size_t)row * DM) : nullptr;
    const float2* p3 = i3 ? reinterpret_cast<const float2*>(i3 + (size_t)row * DM) : nullptr;
    float2 vals[8];
    float s = 0.f, sq = 0.f;
#pragma unroll
    for (int i = 0; i < 8; i++) {
        int j = lane + i * 32;
        float2 v = p1[j];
        if (p2) { float2 w = p2[j]; v.x += w.x; v.y += w.y; }
        if (p3) { float2 w = p3[j]; v.x += w.x; v.y += w.y; }
        vals[i] = v;
        s += v.x + v.y; sq += v.x * v.x + v.y * v.y;
    }
#pragma unroll
    for (int o = 16; o; o >>= 1) {
        s  += __shfl_xor_sync(0xffffffffu, s, o);
        sq += __shfl_xor_sync(0xffffffffu, sq, o);
    }
    float m = s * (1.f / DM);
    float var = sq * (1.f / DM) - m * m;
    float r = rsqrtf(var + 1e-5f);
    const float2* gp = reinterpret_cast<const float2*>(g);
    const float2* bp = reinterpret_cast<const float2*>(bta);
    float2* op = reinterpret_cast<float2*>(out + (size_t)row * DM);
#pragma unroll
    for (int i = 0; i < 8; i++) {
        int j = lane + i * 32;
        float2 gv = gp[j], bv = bp[j];
        float o0 = (vals[i].x - m) * r * gv.x + bv.x;
        float o1 = (vals[i].y - m) * r * gv.y + bv.y;
        op[j] = make_float2(o0, o1);
        if (out_s) {
            uint32_t hi, lo;
            split2(o0, o1, hi, lo);
            size_t o = (size_t)row * DM + ((j >> 4) * 32) + (j & 15);
            out_s[o] = hi; out_s[o + 16] = lo;
        }
    }
}

__global__ void out_kernel(const float* __restrict__ dec,
                           const float* __restrict__ means,
                           const float* __restrict__ stds,
                           float* __restrict__ out)
{
    int idx = blockIdx.x * blockDim.x + threadIdx.x;
    if (idx >= BATCH * PRED * NVARS) return;
    int b = idx / (PRED * NVARS);
    int rem = idx - b * (PRED * NVARS);
    int p = rem / NVARS;
    int n = rem - p * NVARS;
    float v = dec[((size_t)b * LTOK + n) * PRED + p];
    out[idx] = v * stds[b * NVARS + n] + means[b * NVARS + n];
}

// ================= host orchestration ======================================
template <int ACT, int OUT>
static void launch_mma(const uint32_t* A, int ldaw, const uint32_t* W,
                       const float* bias, float* C, int ldc, uint32_t* Cs,
                       int M, int N, int K,
                       const float* e1 = nullptr, const float* e2 = nullptr,
                       uint32_t* Cs2 = nullptr,
                       int Z = 1, size_t zsA = 0, size_t zsW = 0,
                       size_t zsC = 0, size_t zsBias = 0)
{
    dim3 grid(CDIV(N, BN), CDIV(M, BM), Z);
    mma_gemm<ACT, OUT><<<grid, 256, SMEM_GEMM>>>(A, ldaw, W, bias, C, ldc, Cs,
                                                 M, N, K, e1, e2, Cs2,
                                                 zsA, zsW, zsC, zsBias);
}

static void wsplit(const float* src, uint32_t* dst, int rows, int K)
{
    wsplit_kernel<<<CDIV(rows * (K / 2), 256), 256>>>(src, dst, rows, K);
}

extern "C" void kernel_launch(void* const* d_in, const int* in_sizes, int n_in,
                              void* d_out, int out_size)
{
    const float* x_enc    = (const float*)d_in[0];
    const float* x_mark   = (const float*)d_in[1];
    const float* emb_w    = (const float*)d_in[4];
    const float* emb_b    = (const float*)d_in[5];
    const float* in_proj  = (const float*)d_in[6];
    const float* conv_w   = (const float*)d_in[7];
    const float* conv_b   = (const float*)d_in[8];
    const float* x_proj   = (const float*)d_in[9];
    const float* dt_w     = (const float*)d_in[10];
    const float* dt_b     = (const float*)d_in[11];
    const float* A_log    = (const float*)d_in[12];
    const float* D_param  = (const float*)d_in[13];
    const float* out_w    = (const float*)d_in[14];
    const float* ffn_w1   = (const float*)d_in[15];
    const float* ffn_b1   = (const float*)d_in[16];
    const float* ffn_w2   = (const float*)d_in[17];
    const float* ffn_b2   = (const float*)d_in[18];
    const float* ln1_g    = (const float*)d_in[19];
    const float* ln1_b    = (const float*)d_in[20];
    const float* ln2_g    = (const float*)d_in[21];
    const float* ln2_b    = (const float*)d_in[22];
    const float* fin_g    = (const float*)d_in[23];
    const float* fin_b    = (const float*)d_in[24];
    const float* gate_w   = (const float*)d_in[25];
    const float* gate_b   = (const float*)d_in[26];
    const float* proj_w   = (const float*)d_in[27];
    const float* proj_b   = (const float*)d_in[28];

    cudaFuncSetAttribute((const void*)mma_gemm<ACT_DUP, 2>,
                         cudaFuncAttributeMaxDynamicSharedMemorySize, SMEM_GEMM);
    cudaFuncSetAttribute((const void*)mma_gemm<ACT_NONE, 0>,
                         cudaFuncAttributeMaxDynamicSharedMemorySize, SMEM_GEMM);
    cudaFuncSetAttribute((const void*)mma_gemm<ACT_DELTABC, 0>,
                         cudaFuncAttributeMaxDynamicSharedMemorySize, SMEM_GEMM);
    cudaFuncSetAttribute((const void*)mma_gemm<ACT_RELU, 1>,
                         cudaFuncAttributeMaxDynamicSharedMemorySize, SMEM_GEMM);
    cudaFuncSetAttribute((const void*)mma_gemm<ACT_GATE, 1>,
                         cudaFuncAttributeMaxDynamicSharedMemorySize, SMEM_GEMM);

    float* S = nullptr;
    cudaGetSymbolAddress((void**)&S, g_scratch);
    uint32_t* U = reinterpret_cast<uint32_t*>(S);

    uint32_t* tok_s = U + OFF_TOKS;
    float* dec   = S + OFF_DEC;
    float* enc   = S + OFF_ENC;
    uint32_t* enc_s = U + OFF_ENCS;
    float* raw   = S + OFF_RAW;
    uint32_t* raw_s = U + OFF_RAWS;
    float* xzB   = S + OFF_XZB;
    uint32_t* xc_s = U + OFF_XCS;
    float* dx    = S + OFF_DX;
    float* bcb   = S + OFF_BC;
    uint32_t* yp_s = U + OFF_YPS;
    float* mo    = S + OFF_MO;
    float* t1    = S + OFF_T1;
    uint32_t* t1_s = U + OFF_T1S;
    float* t2    = S + OFF_T2;
    uint32_t* t2_s = U + OFF_T2S;
    float* t3    = S + OFF_T3;
    uint32_t* wc_s  = U + OFF_WCS;
    uint32_t* emb_ws = U + OFF_EMBS;
    uint32_t* inp_ws = U + OFF_INPS;
    uint32_t* out_ws = U + OFF_OUTS;
    uint32_t* f1_ws  = U + OFF_F1S;
    uint32_t* f2_ws  = U + OFF_F2S;
    uint32_t* g_ws   = U + OFF_GWS;
    uint32_t* p_ws   = U + OFF_PWS;
    float* means = S + OFF_MEAN;
    float* stds  = S + OFF_STD;
    float* Pbuf  = S + OFF_P;
    float* Hlbuf = S + OFF_HL;
    float* Hibuf = S + OFF_HI;

    // weight pre-split
    wsplit(emb_w,   emb_ws, 512, 96);
    wsplit(in_proj, inp_ws, 4096, 512);
    wsplit(out_w,   out_ws, 2048, 512);
    wsplit(ffn_w1,  f1_ws,  1024, 512);
    wsplit(ffn_w2,  f2_ws,  1024, 512);
    wsplit(gate_w,  g_ws,   512, 512);
    wsplit(proj_w,  p_ws,   96, 512);
    wcomb_kernel<<<CDIV(4 * 544 * 256, 256), 256>>>(dt_w, x_proj, wc_s);

    stats_kernel<<<CDIV(BATCH * NVARS, 256), 256>>>(x_enc, means, stds);
    tok_kernel<<<CDIV(TTOK * 48, 256), 256>>>(x_enc, x_mark, means, stds, tok_s);

    // embedding GEMM -> enc (fp32+split) and raw (fp32+split)
    launch_mma<ACT_DUP, 2>(tok_s, 96, emb_ws, emb_b, enc, DM, enc_s,
                           TTOK, DM, 96, nullptr, raw, raw_s);

    for (int l = 0; l < NL; l++) {
        // merged fwd+rev in_proj: N=2048, fp32 out
        launch_mma<ACT_NONE, 0>(enc_s, DM, inp_ws + (size_t)l * 2048 * 512,
                                nullptr, xzB, 4 * DM, nullptr,
                                TTOK, 4 * DM, DM);
        conv_silu_kernel<<<CDIV(2 * TTOK * 256, 256), 256>>>(
            xzB, conv_w + (size_t)l * 2 * DM * 2, conv_b + (size_t)l * 2 * DM,
            xc_s, dx);

        // fused delta(softplus)+B+C GEMM, z=2 -> dx / bcb
        launch_mma<ACT_DELTABC, 0>(xc_s, DM, wc_s + (size_t)l * 2 * 544 * 512,
                                   dt_b + (size_t)l * 2 * DM, dx, 2048, nullptr,
                                   TTOK, 544, DM, bcb, nullptr, nullptr,
                                   2, (size_t)TTOK * DM, (size_t)544 * 512,
                                   1024, DM);

        // chunked scan
        scan_p1<<<NWARP / 8, 256>>>(dx, bcb,
                                    A_log + (size_t)l * 2 * DM * DS,
                                    Pbuf, Hlbuf);
        scan_comb<<<CDIV(2 * BATCH * DM * 16, 256), 256>>>(Pbuf, Hlbuf, Hibuf);
        scan_p2<<<NWARP / 8, 256>>>(dx, bcb, xzB,
                                    A_log + (size_t)l * 2 * DM * DS,
                                    D_param + (size_t)l * 2 * DM,
                                    Hibuf, yp_s);

        // out projection, z=2 -> mo fp32
        launch_mma<ACT_NONE, 0>(yp_s, DM, out_ws + (size_t)l * 2 * 512 * 512,
                                nullptr, mo, DM, nullptr,
                                TTOK, DM, DM, nullptr, nullptr, nullptr,
                                2, (size_t)TTOK * DM, (size_t)512 * 512,
                                (size_t)TTOK * DM, 0);

        ln_kernel<<<CDIV(TTOK, 8), 256>>>(enc, mo, mo + (size_t)TTOK * DM,
                                          ln1_g + l * DM, ln1_b + l * DM,
                                          t1, t1_s);
        // FFN1: relu, split-only output t2_s
        launch_mma<ACT_RELU, 1>(t1_s, DM, f1_ws + (size_t)l * 512 * 512,
                                ffn_b1 + l * DFF, nullptr, DFF, t2_s,
                                TTOK, DFF, DM);
        // FFN2: fp32 out t3
        launch_mma<ACT_NONE, 0>(t2_s, DFF, f2_ws + (size_t)l * 512 * 512,
                                ffn_b2 + l * DM, t3, DM, nullptr,
                                TTOK, DM, DFF);
        ln_kernel<<<CDIV(TTOK, 8), 256>>>(t1, t3, nullptr,
                                          ln2_g + l * DM, ln2_b + l * DM,
                                          enc, enc_s);
    }

    // final LN -> t2 (fp32 only)
    ln_kernel<<<CDIV(TTOK, 8), 256>>>(enc, nullptr, nullptr, fin_g, fin_b,
                                      t2, nullptr);
    // gated residual: t1_s = split(t2 + sigmoid(raw@gate^T+b)*raw)
    launch_mma<ACT_GATE, 1>(raw_s, DM, g_ws, gate_b, nullptr, DM, t1_s,
                            TTOK, DM, DM, t2, raw);
    // projection to PRED -> dec fp32
    launch_mma<ACT_NONE, 0>(t1_s, DM, p_ws, proj_b, dec, PRED, nullptr,
                            TTOK, PRED, DM);
    out_kernel<<<CDIV(BATCH * PRED * NVARS, 256), 256>>>(dec, means, stds,
                                                         (float*)d_out);
}

// round 8
// speedup vs baseline: 1.0248x; 1.0248x over previous
#include <cuda_runtime.h>
#include <cuda_bf16.h>
#include <math.h>
#include <stdint.h>

// ---------------- problem constants ----------------
#define BATCH 8
#define SEQ   96
#define PRED  96
#define NVARS 862
#define NMARK 4
#define LTOK  866
#define TTOK  (BATCH*LTOK)   // 6928
#define DM    512
#define DS    16
#define DFF   512
#define RK    32
#define NL    2

// chunked scan
#define NCH   32
#define CHL   28
#define NWARP (2*BATCH*16*NCH)
#define NSTATE ((size_t)NWARP*32*16)

#define CDIV(a,b) (((a)+(b)-1)/(b))

// ================= scratch (static; no allocs) =============================
constexpr size_t OFF_TOKS = 0;                                   // split [TTOK][96w]
constexpr size_t OFF_DEC  = OFF_TOKS + (size_t)TTOK*96;
constexpr size_t OFF_ENC  = OFF_DEC  + (size_t)TTOK*96;          // fp32
constexpr size_t OFF_ENCS = OFF_ENC  + (size_t)TTOK*DM;          // split
constexpr size_t OFF_RAW  = OFF_ENCS + (size_t)TTOK*DM;
constexpr size_t OFF_RAWS = OFF_RAW  + (size_t)TTOK*DM;
constexpr size_t OFF_XZB  = OFF_RAWS + (size_t)TTOK*DM;          // [T,2048] fp32
constexpr size_t OFF_XCS  = OFF_XZB  + (size_t)TTOK*4*DM;        // split [2][T][512w]
constexpr size_t OFF_DX   = OFF_XCS  + (size_t)2*TTOK*DM;        // [T,2048] (dlt,x)
constexpr size_t OFF_BC   = OFF_DX   + (size_t)TTOK*2048;        // [T,64] (B,C)
constexpr size_t OFF_YPS  = OFF_BC   + (size_t)TTOK*64;          // split [2][T][512w]
constexpr size_t OFF_MO   = OFF_YPS  + (size_t)2*TTOK*DM;        // fp32 [2][T][512]
constexpr size_t OFF_T1   = OFF_MO   + (size_t)2*TTOK*DM;
constexpr size_t OFF_T1S  = OFF_T1   + (size_t)TTOK*DM;
constexpr size_t OFF_T2   = OFF_T1S  + (size_t)TTOK*DM;
constexpr size_t OFF_T2S  = OFF_T2   + (size_t)TTOK*DM;
constexpr size_t OFF_T3   = OFF_T2S  + (size_t)TTOK*DM;
constexpr size_t OFF_WCS  = OFF_T3   + (size_t)TTOK*DM;          // [4][544][512w]
constexpr size_t OFF_EMBS = OFF_WCS  + (size_t)4*544*512;
constexpr size_t OFF_INPS = OFF_EMBS + (size_t)512*96;
constexpr size_t OFF_OUTS = OFF_INPS + (size_t)4096*512;
constexpr size_t OFF_F1S  = OFF_OUTS + (size_t)2048*512;
constexpr size_t OFF_F2S  = OFF_F1S  + (size_t)1024*512;
constexpr size_t OFF_GWS  = OFF_F2S  + (size_t)1024*512;
constexpr size_t OFF_PWS  = OFF_GWS  + (size_t)512*512;
constexpr size_t OFF_MEAN = OFF_PWS  + (size_t)96*512;
constexpr size_t OFF_STD  = OFF_MEAN + (size_t)BATCH*NVARS;
constexpr size_t OFF_P    = OFF_STD  + (size_t)BATCH*NVARS;
constexpr size_t OFF_HL   = OFF_P    + NSTATE;
constexpr size_t OFF_HI   = OFF_HL   + NSTATE;
constexpr size_t SCRATCH_FLOATS = OFF_HI + NSTATE;

__device__ float g_scratch[SCRATCH_FLOATS];

// ---- bf16 hi/lo split helpers ----
__device__ __forceinline__ uint32_t pack_bf16(float a, float b) {
    __nv_bfloat162 t = __floats2bfloat162_rn(a, b);
    return *reinterpret_cast<uint32_t*>(&t);
}
__device__ __forceinline__ void split2(float v0, float v1,
                                       uint32_t& hi, uint32_t& lo) {
    float h0 = __bfloat162float(__float2bfloat16_rn(v0));
    float h1 = __bfloat162float(__float2bfloat16_rn(v1));
    hi = pack_bf16(h0, h1);
    lo = pack_bf16(v0 - h0, v1 - h1);
}
__device__ __forceinline__ int sw_idx(int c) {   // c even
    return (c >> 5) * 32 + ((c & 31) >> 1);
}

// ================= bf16-split tensor-core GEMM (cp.async 3-stage) ==========
enum { ACT_NONE = 0, ACT_RELU = 1, ACT_DELTABC = 2, ACT_GATE = 3, ACT_DUP = 4 };
// OUT: 0 = fp32 only, 1 = split only, 2 = both

#define BM 64
#define BN 128
#define LPITCH 36
#define ROWB 144
#define A_TILE_W (64*LPITCH)
#define B_TILE_W (128*LPITCH)
#define STAGE_W  (A_TILE_W + B_TILE_W)      // 6912 words
#define GST 3
#define SMEM_GEMM (GST*STAGE_W*4)           // 82944 bytes

__device__ __forceinline__ uint32_t smem_u32(const void* p) {
    uint32_t a;
    asm("{ .reg .u64 t; cvta.to.shared.u64 t, %1; cvt.u32.u64 %0, t; }"
        : "=r"(a) : "l"(p));
    return a;
}

__device__ __forceinline__ void cp16(uint32_t dst, const void* src, uint32_t sz) {
    asm volatile("cp.async.ca.shared.global [%0], [%1], 16, %2;"
        :: "r"(dst), "l"(src), "r"(sz) : "memory");
}
#define CP_COMMIT() asm volatile("cp.async.commit_group;" ::: "memory")
#define CP_WAIT1()  asm volatile("cp.async.wait_group 1;" ::: "memory")

#define LDSM_X4(r0,r1,r2,r3,addr) \
    asm volatile("ldmatrix.sync.aligned.m8n8.x4.shared.b16 {%0,%1,%2,%3}, [%4];" \
        : "=r"(r0),"=r"(r1),"=r"(r2),"=r"(r3) : "r"(addr))

#define MMA_BF16(d,a,b0,b1) \
    asm volatile("mma.sync.aligned.m16n8k16.row.col.f32.bf16.bf16.f32 " \
        "{%0,%1,%2,%3}, {%4,%5,%6,%7}, {%8,%9}, {%0,%1,%2,%3};" \
        : "+f"((d)[0]),"+f"((d)[1]),"+f"((d)[2]),"+f"((d)[3]) \
        : "r"((a)[0]),"r"((a)[1]),"r"((a)[2]),"r"((a)[3]), "r"(b0),"r"(b1))

template <int ACT, int OUT>
__global__ void __launch_bounds__(256, 2)
mma_gemm(const uint32_t* __restrict__ A, int ldaw,
         const uint32_t* __restrict__ W,
         const float* __restrict__ bias,
         float* __restrict__ C, int ldc,
         uint32_t* __restrict__ Cs,
         int M, int N, int K,
         const float* __restrict__ e1, const float* __restrict__ e2,
         uint32_t* __restrict__ Cs2,
         size_t zsA, size_t zsW, size_t zsC, size_t zsBias)
{
    extern __shared__ char smem[];
    const uint32_t sbase = smem_u32(smem);
    const int tid  = threadIdx.x;
    const int lane = tid & 31;
    const int wid  = tid >> 5;
    const int warp_m = wid & 1;
    const int warp_n = wid >> 1;
    const int bm = blockIdx.y * BM, bn = blockIdx.x * BN;

    A += blockIdx.z * zsA;
    W += blockIdx.z * zsW;
    if (C) C += blockIdx.z * zsC;
    if (bias) bias += blockIdx.z * zsBias;

    const int q4  = tid & 7;            // 16B chunk within 32-word row
    const int r0g = tid >> 3;           // base row (0..31)

    const int KT = K / 32;

    auto issue_stage = [&](int kt, int s) {
        if (kt >= KT) return;
        uint32_t sa = sbase + s * (STAGE_W * 4);
        uint32_t sb = sa + A_TILE_W * 4;
#pragma unroll
        for (int i = 0; i < 2; i++) {
            int r = r0g + i * 32;
            int gr = bm + r;
            cp16(sa + r * ROWB + q4 * 16,
                 A + (size_t)gr * ldaw + kt * 32 + q4 * 4,
                 (gr < M) ? 16u : 0u);
        }
#pragma unroll
        for (int i = 0; i < 4; i++) {
            int r = r0g + i * 32;
            int gn = bn + r;
            cp16(sb + r * ROWB + q4 * 16,
                 W + (size_t)gn * K + kt * 32 + q4 * 4,
                 (gn < N) ? 16u : 0u);
        }
    };

    const uint32_t a_off = (uint32_t)(warp_m * 32 + (lane & 15)) * ROWB + ((lane >> 4) * 16);
    const uint32_t b_off = (uint32_t)(warp_n * 32 + ((lane >> 4) & 1) * 8 + (lane & 7)) * ROWB
                         + (((lane >> 3) & 1) * 16);

    float acc[2][4][4];
#pragma unroll
    for (int i = 0; i < 2; i++)
#pragma unroll
        for (int j = 0; j < 4; j++)
#pragma unroll
            for (int e = 0; e < 4; e++) acc[i][j][e] = 0.f;

    issue_stage(0, 0); CP_COMMIT();
    issue_stage(1, 1); CP_COMMIT();

    int sidx = 0;          // stage of kt
    int snext = 2;         // stage for kt+2
    for (int kt = 0; kt < KT; kt++) {
        CP_WAIT1();
        __syncthreads();
        issue_stage(kt + 2, snext);
        CP_COMMIT();
        const uint32_t Ab = sbase + sidx * (STAGE_W * 4);
        const uint32_t Bb = Ab + A_TILE_W * 4;
#pragma unroll
        for (int ks = 0; ks < 6; ks++) {
            const int kk = ks & 1;
            const int segA = (ks == 2 || ks == 3) ? 1 : 0;
            const int segB = (ks >= 4) ? 1 : 0;
            const uint32_t ao = Ab + a_off + segA * 64 + kk * 32;
            const uint32_t bo = Bb + b_off + segB * 64 + kk * 32;
            uint32_t a[2][4];
#pragma unroll
            for (int mt = 0; mt < 2; mt++)
                LDSM_X4(a[mt][0], a[mt][1], a[mt][2], a[mt][3], ao + mt * 16 * ROWB);
            uint32_t b[2][4];
#pragma unroll
            for (int p = 0; p < 2; p++)
                LDSM_X4(b[p][0], b[p][1], b[p][2], b[p][3], bo + p * 16 * ROWB);
#pragma unroll
            for (int mt = 0; mt < 2; mt++) {
                MMA_BF16(acc[mt][0], a[mt], b[0][0], b[0][1]);
                MMA_BF16(acc[mt][1], a[mt], b[0][2], b[0][3]);
                MMA_BF16(acc[mt][2], a[mt], b[1][0], b[1][1]);
                MMA_BF16(acc[mt][3], a[mt], b[1][2], b[1][3]);
            }
        }
        sidx = (sidx == GST - 1) ? 0 : sidx + 1;
        snext = (snext == GST - 1) ? 0 : snext + 1;
    }

    // ---- epilogue ----
    const int er = bm + warp_m * 32 + (lane >> 2);
    const int ec = bn + warp_n * 32 + (lane & 3) * 2;
#pragma unroll
    for (int mt = 0; mt < 2; mt++) {
#pragma unroll
        for (int nt = 0; nt < 4; nt++) {
            int gc = ec + nt * 8;
            if (gc >= N) continue;
            float b0 = 0.f, b1 = 0.f;
            if (bias) {
                if (ACT == ACT_DELTABC) {
                    if (gc < 512)     b0 = bias[gc];
                    if (gc + 1 < 512) b1 = bias[gc + 1];
                } else {
                    b0 = bias[gc]; b1 = bias[gc + 1];
                }
            }
#pragma unroll
            for (int h = 0; h < 2; h++) {
                int gr = er + mt * 16 + h * 8;
                if (gr >= M) continue;
                float v0 = acc[mt][nt][h * 2 + 0];
                float v1 = acc[mt][nt][h * 2 + 1];
                if (ACT == ACT_DELTABC) {
                    float* bco = const_cast<float*>(e1) + blockIdx.z * 32;
                    if (gc < 512) {
                        v0 += b0; v1 += b1;
                        v0 = fmaxf(v0, 0.f) + log1pf(__expf(-fabsf(v0)));
                        v1 = fmaxf(v1, 0.f) + log1pf(__expf(-fabsf(v1)));
                        C[(size_t)gr * 2048 + 2 * gc]     = v0;
                        C[(size_t)gr * 2048 + 2 * gc + 2] = v1;
                    } else if (gc < 528) {
                        int s = gc - 512;
                        bco[(size_t)gr * 64 + 2 * s]     = v0;
                        bco[(size_t)gr * 64 + 2 * s + 2] = v1;
                    } else if (gc < 544) {
                        int s = gc - 528;
                        bco[(size_t)gr * 64 + 2 * s + 1] = v0;
                        bco[(size_t)gr * 64 + 2 * s + 3] = v1;
                    }
                    continue;
                }
                v0 += b0; v1 += b1;
                if (ACT == ACT_RELU) { v0 = fmaxf(v0, 0.f); v1 = fmaxf(v1, 0.f); }
                if (ACT == ACT_GATE) {
                    size_t ix = (size_t)gr * ldc + gc;
                    float s0 = 1.f / (1.f + __expf(-v0));
                    float s1 = 1.f / (1.f + __expf(-v1));
                    v0 = e1[ix] + s0 * e2[ix];
                    v1 = e1[ix + 1] + s1 * e2[ix + 1];
                }
                if (OUT == 0 || OUT == 2)
                    *reinterpret_cast<float2*>(&C[(size_t)gr * ldc + gc]) =
                        make_float2(v0, v1);
                if (OUT >= 1) {
                    uint32_t hi, lo;
                    split2(v0, v1, hi, lo);
                    size_t o = (size_t)gr * N + sw_idx(gc);
                    Cs[o] = hi; Cs[o + 16] = lo;
                }
                if (ACT == ACT_DUP) {
                    size_t ix = (size_t)gr * ldc + gc;
                    *reinterpret_cast<float2*>(const_cast<float*>(&e2[ix])) =
                        make_float2(v0, v1);
                    uint32_t hi, lo;
                    split2(v0, v1, hi, lo);
                    size_t o = (size_t)gr * N + sw_idx(gc);
                    Cs2[o] = hi; Cs2[o + 16] = lo;
                }
            }
        }
    }
}

// ================= one-shot weight split (all weights, 1 launch) ===========
__device__ __forceinline__ void wsplit_one(const float* __restrict__ src,
                                           uint32_t* __restrict__ dst,
                                           int K, int idx)
{
    int K2 = K >> 1;
    int row = idx / K2, j = idx - row * K2;
    float v0 = src[(size_t)row * K + 2 * j];
    float v1 = src[(size_t)row * K + 2 * j + 1];
    uint32_t hi, lo;
    split2(v0, v1, hi, lo);
    size_t o = (size_t)row * K + (j >> 4) * 32 + (j & 15);
    dst[o] = hi; dst[o + 16] = lo;
}

#define N_EMB (512*48)
#define N_INP (4096*256)
#define N_OUT (2048*256)
#define N_F1  (1024*256)
#define N_F2  (1024*256)
#define N_GW  (512*256)
#define N_PW  (96*256)
#define N_ALL (N_EMB+N_INP+N_OUT+N_F1+N_F2+N_GW+N_PW)

__global__ void wsplit_all(const float* __restrict__ emb, uint32_t* emb_d,
                           const float* __restrict__ inp, uint32_t* inp_d,
                           const float* __restrict__ outw, uint32_t* out_d,
                           const float* __restrict__ f1, uint32_t* f1_d,
                           const float* __restrict__ f2, uint32_t* f2_d,
                           const float* __restrict__ gw, uint32_t* g_d,
                           const float* __restrict__ pw, uint32_t* p_d)
{
    int idx = blockIdx.x * blockDim.x + threadIdx.x;
    if (idx >= N_ALL) return;
    if (idx < N_EMB) { wsplit_one(emb, emb_d, 96, idx); return; }
    idx -= N_EMB;
    if (idx < N_INP) { wsplit_one(inp, inp_d, 512, idx); return; }
    idx -= N_INP;
    if (idx < N_OUT) { wsplit_one(outw, out_d, 512, idx); return; }
    idx -= N_OUT;
    if (idx < N_F1)  { wsplit_one(f1, f1_d, 512, idx); return; }
    idx -= N_F1;
    if (idx < N_F2)  { wsplit_one(f2, f2_d, 512, idx); return; }
    idx -= N_F2;
    if (idx < N_GW)  { wsplit_one(gw, g_d, 512, idx); return; }
    idx -= N_GW;
    wsplit_one(pw, p_d, 512, idx);
}

// ================= small kernels ==========================================
__global__ void stats_kernel(const float* __restrict__ x_enc,
                             float* __restrict__ means, float* __restrict__ stds)
{
    int idx = blockIdx.x * blockDim.x + threadIdx.x;
    if (idx >= BATCH * NVARS) return;
    int b = idx / NVARS, n = idx - b * NVARS;
    float s = 0.f, sq = 0.f;
    for (int t = 0; t < SEQ; t++) {
        float v = x_enc[((size_t)b * SEQ + t) * NVARS + n];
        s += v; sq += v * v;
    }
    float m = s * (1.f / SEQ);
    float var = sq * (1.f / SEQ) - m * m;
    means[idx] = m;
    stds[idx] = sqrtf(var + 1e-5f);
}

__global__ void tok_kernel(const float* __restrict__ x_enc,
                           const float* __restrict__ x_mark,
                           const float* __restrict__ means,
                           const float* __restrict__ stds,
                           uint32_t* __restrict__ tok_s)
{
    int idx = blockIdx.x * blockDim.x + threadIdx.x;
    if (idx >= TTOK * 48) return;
    int j = idx % 48;
    int t = idx / 48;
    int b = t / LTOK, v = t - b * LTOK;
    int s0 = 2 * j, s1 = 2 * j + 1;
    float val0, val1;
    if (v < NVARS) {
        float m = means[b * NVARS + v], sd = stds[b * NVARS + v];
        val0 = (x_enc[((size_t)b * SEQ + s0) * NVARS + v] - m) / sd;
        val1 = (x_enc[((size_t)b * SEQ + s1) * NVARS + v] - m) / sd;
    } else {
        val0 = x_mark[((size_t)b * SEQ + s0) * NMARK + (v - NVARS)];
        val1 = x_mark[((size_t)b * SEQ + s1) * NMARK + (v - NVARS)];
    }
    uint32_t hi, lo;
    split2(val0, val1, hi, lo);
    size_t o = (size_t)t * 96 + (j >> 4) * 32 + (j & 15);
    tok_s[o] = hi; tok_s[o + 16] = lo;
}

__global__ void wcomb_kernel(const float* __restrict__ dtw,
                             const float* __restrict__ xpw,
                             uint32_t* __restrict__ wcs)
{
    int idx = blockIdx.x * blockDim.x + threadIdx.x;
    if (idx >= 4 * 544 * 256) return;
    int w = idx / (544 * 256);
    int rem = idx - w * 544 * 256;
    int n = rem >> 8;
    int k2 = rem & 255;
    int k = 2 * k2;
    float v0, v1;
    if (n < 512) {
        const float* dr = dtw + ((size_t)w * 512 + n) * 32;
        const float* xr = xpw + (size_t)w * 64 * 512 + k;
        v0 = 0.f; v1 = 0.f;
#pragma unroll
        for (int r = 0; r < 32; r++) {
            float dv = dr[r];
            v0 = fmaf(dv, xr[(size_t)r * 512], v0);
            v1 = fmaf(dv, xr[(size_t)r * 512 + 1], v1);
        }
    } else {
        const float* xr = xpw + (size_t)w * 64 * 512 + (size_t)(32 + n - 512) * 512;
        v0 = xr[k]; v1 = xr[k + 1];
    }
    uint32_t hi, lo;
    split2(v0, v1, hi, lo);
    size_t o = ((size_t)w * 544 + n) * 512 + (k2 >> 4) * 32 + (k2 & 15);
    wcs[o] = hi; wcs[o + 16] = lo;
}

__global__ void conv_silu_kernel(const float* __restrict__ xzB,
                                 const float* __restrict__ cw,
                                 const float* __restrict__ cb,
                                 uint32_t* __restrict__ xcs,
                                 float* __restrict__ dx)
{
    int idx = blockIdx.x * blockDim.x + threadIdx.x;
    const int n = TTOK * 256;
    if (idx >= 2 * n) return;
    int dir = idx >= n;
    int r = idx - dir * n;
    int d2 = r & 255;
    int t = r >> 8;
    int d = 2 * d2;
    int b = t / LTOK, l = t - b * LTOK;
    const float* base = xzB + (size_t)dir * 1024;
    float2 cur = *reinterpret_cast<const float2*>(base + (size_t)t * 2048 + d);
    int ln = dir ? (l + 1) : (l - 1);
    float2 nbv = make_float2(0.f, 0.f);
    if (ln >= 0 && ln < LTOK)
        nbv = *reinterpret_cast<const float2*>(base + (size_t)(t + (dir ? 1 : -1)) * 2048 + d);
    float4 wv = *reinterpret_cast<const float4*>(cw + (size_t)dir * 1024 + 2 * d);
    float2 cbv = *reinterpret_cast<const float2*>(cb + (size_t)dir * 512 + d);
    float v0 = wv.x * nbv.x + wv.y * cur.x + cbv.x;
    float v1 = wv.z * nbv.y + wv.w * cur.y + cbv.y;
    float o0 = v0 / (1.f + __expf(-v0));
    float o1 = v1 / (1.f + __expf(-v1));
    dx[(size_t)t * 2048 + dir * 1024 + 2 * d + 1] = o0;
    dx[(size_t)t * 2048 + dir * 1024 + 2 * d + 3] = o1;
    uint32_t hi, lo;
    split2(o0, o1, hi, lo);
    size_t o = ((size_t)dir * TTOK + t) * 512 + (d2 >> 4) * 32 + (d2 & 15);
    xcs[o] = hi; xcs[o + 16] = lo;
}

// ---------------- chunked selective scan -----------------------------------
__global__ void __launch_bounds__(256)
scan_p1(const float* __restrict__ dx, const float* __restrict__ bcb,
        const float* __restrict__ A_log_l,
        float* __restrict__ P, float* __restrict__ H)
{
    int w = blockIdx.x * 8 + (threadIdx.x >> 5);
    int lane = threadIdx.x & 31;
    int ch = w & 31;
    int dblk = (w >> 5) & 15;
    int b = (w >> 9) & 7;
    int dir = w >> 12;
    int d = dblk * 32 + lane;

    float a[DS];
    bool structured = true;
#pragma unroll
    for (int s = 0; s < DS; s++) {
        a[s] = -__expf(A_log_l[((size_t)dir * DM + d) * DS + s]) * 1.44269504f;
        structured = structured &&
            (fabsf(a[s] - a[0] * (s + 1)) <= 1e-4f * fabsf(a[0] * (s + 1)));
    }

    float h[DS], Pr[DS];
#pragma unroll
    for (int s = 0; s < DS; s++) { h[s] = 0.f; Pr[s] = 1.f; }

    int i0 = ch * CHL;
    int nn = LTOK - i0; if (nn > CHL) nn = CHL; if (nn < 0) nn = 0;
    int l0 = dir ? (LTOK - 1 - i0) : i0;
    long t0 = (long)b * LTOK + l0;
    long stp = dir ? -1 : 1;
    const float2* dxp = (const float2*)dx + t0 * 1024 + dir * 512 + d;
    const float2* bp  = (const float2*)bcb + t0 * 32 + dir * 16;
    long sdx = stp * 1024, sbc = stp * 32;

    if (structured) {
        const float a0 = a[0];
        for (int i = 0; i < nn; i++) {
            float2 dv = *dxp;
            float u = dv.x * dv.y;
            float q = exp2f(dv.x * a0);
            float dA = 1.f;
#pragma unroll
            for (int s = 0; s < DS; s++) {
                dA *= q;
                float2 bcv = bp[s];
                Pr[s] *= dA;
                h[s] = fmaf(dA, h[s], bcv.x * u);
            }
            dxp += sdx; bp += sbc;
        }
    } else {
        for (int i = 0; i < nn; i++) {
            float2 dv = *dxp;
            float u = dv.x * dv.y;
#pragma unroll
            for (int s = 0; s < DS; s++) {
                float2 bcv = bp[s];
                float dA = exp2f(dv.x * a[s]);
                Pr[s] *= dA;
                h[s] = fmaf(dA, h[s], bcv.x * u);
            }
            dxp += sdx; bp += sbc;
        }
    }
    float* Po = P + ((size_t)w * 32 + lane) * 16;
    float* Ho = H + ((size_t)w * 32 + lane) * 16;
#pragma unroll
    for (int s = 0; s < DS; s++) { Po[s] = Pr[s]; Ho[s] = h[s]; }
}

__global__ void scan_comb(const float* __restrict__ P,
                          const float* __restrict__ Hl,
                          float* __restrict__ Hin)
{
    int idx = blockIdx.x * blockDim.x + threadIdx.x;
    if (idx >= 2 * BATCH * DM * 16) return;
    int s = idx & 15;
    int lane = (idx >> 4) & 31;
    int dblk = (idx >> 9) & 15;
    int b = (idx >> 13) & 7;
    int dir = idx >> 16;
    size_t w0 = (size_t)dir * 4096 + (size_t)b * 512 + (size_t)dblk * 32;
    float h = 0.f;
#pragma unroll
    for (int ch = 0; ch < NCH; ch++) {
        size_t o = ((w0 + ch) * 32 + lane) * 16 + s;
        Hin[o] = h;
        h = P[o] * h + Hl[o];
    }
}

__global__ void __launch_bounds__(256)
scan_p2(const float* __restrict__ dx, const float* __restrict__ bcb,
        const float* __restrict__ xzB,
        const float* __restrict__ A_log_l,
        const float* __restrict__ Dp_l,
        const float* __restrict__ Hin,
        uint32_t* __restrict__ yps)
{
    int w = blockIdx.x * 8 + (threadIdx.x >> 5);
    int lane = threadIdx.x & 31;
    int ch = w & 31;
    int dblk = (w >> 5) & 15;
    int b = (w >> 9) & 7;
    int dir = w >> 12;
    int d = dblk * 32 + lane;

    float a[DS];
    bool structured = true;
#pragma unroll
    for (int s = 0; s < DS; s++) {
        a[s] = -__expf(A_log_l[((size_t)dir * DM + d) * DS + s]) * 1.44269504f;
        structured = structured &&
            (fabsf(a[s] - a[0] * (s + 1)) <= 1e-4f * fabsf(a[0] * (s + 1)));
    }
    float Dv = Dp_l[dir * DM + d];

    float h[DS];
    const float* Hi = Hin + ((size_t)w * 32 + lane) * 16;
#pragma unroll
    for (int s = 0; s < DS; s++) h[s] = Hi[s];

    int i0 = ch * CHL;
    int nn = LTOK - i0; if (nn > CHL) nn = CHL; if (nn < 0) nn = 0;
    int l0 = dir ? (LTOK - 1 - i0) : i0;
    long t0 = (long)b * LTOK + l0;
    long stp = dir ? -1 : 1;
    const float2* dxp = (const float2*)dx + t0 * 1024 + dir * 512 + d;
    const float2* bp  = (const float2*)bcb + t0 * 32 + dir * 16;
    const float*  zp  = xzB + t0 * 2048 + dir * 1024 + 512 + d;
    uint32_t* ys = yps + ((size_t)dir * TTOK) * 512 + t0 * 512 + dblk * 32 + (lane >> 1);
    long sdx = stp * 1024, sbc = stp * 32, sz = stp * 2048, sy = stp * 512;
    const float a0 = a[0];

    for (int i = 0; i < nn; i++) {
        float2 dv = *dxp;
        float u = dv.x * dv.y;
        float y0 = 0.f, y1 = 0.f, y2 = 0.f, y3 = 0.f;
        if (structured) {
            float q = exp2f(dv.x * a0);
            float dA = 1.f;
#pragma unroll
            for (int s = 0; s < DS; s++) {
                dA *= q;
                float2 bcv = bp[s];
                h[s] = fmaf(dA, h[s], bcv.x * u);
                float t = h[s] * bcv.y;
                if ((s & 3) == 0) y0 += t;
                else if ((s & 3) == 1) y1 += t;
                else if ((s & 3) == 2) y2 += t;
                else y3 += t;
            }
        } else {
#pragma unroll
            for (int s = 0; s < DS; s++) {
                float2 bcv = bp[s];
                float dA = exp2f(dv.x * a[s]);
                h[s] = fmaf(dA, h[s], bcv.x * u);
                float t = h[s] * bcv.y;
                if ((s & 3) == 0) y0 += t;
                else if ((s & 3) == 1) y1 += t;
                else if ((s & 3) == 2) y2 += t;
                else y3 += t;
            }
        }
        float y = (y0 + y1) + (y2 + y3);
        float z = *zp;
        float szl = z / (1.f + __expf(-z));
        float yv = (y + Dv * dv.y) * szl;
        float yn = __shfl_down_sync(0xffffffffu, yv, 1);
        if (!(lane & 1)) {
            uint32_t hi, lo;
            split2(yv, yn, hi, lo);
            ys[0] = hi; ys[16] = lo;
        }
        dxp += sdx; bp += sbc; zp += sz; ys += sy;
    }
}

__global__ void ln_kernel(const float* __restrict__ i1,
                          const float* __restrict__ i2,
                          const float* __restrict__ i3,
                          const float* __restrict__ g,
                          const float* __restrict__ bta,
                          float* __restrict__ out,
                          uint32_t* __restrict__ out_s)
{
    int row = blockIdx.x * (blockDim.x >> 5) + (threadIdx.x >> 5);
    int lane = threadIdx.x & 31;
    if (row >= TTOK) return;
    const float2* p1 = reinterpret_cast<const float2*>(i1 + (size_t)row * DM);
    const float2* p2 = i2 ? reinterpret_cast<const float2*>(i2 + (size_t)row * DM) : nullptr;
    const float2* p3 = i3 ? reinterpret_cast<const float2*>(i3 + (size_t)row * DM) : nullptr;
    float2 vals[8];
    float s = 0.f, sq = 0.f;
#pragma unroll
    for (int i = 0; i < 8; i++) {
        int j = lane + i * 32;
        float2 v = p1[j];
        if (p2) { float2 w = p2[j]; v.x += w.x; v.y += w.y; }
        if (p3) { float2 w = p3[j]; v.x += w.x; v.y += w.y; }
        vals[i] = v;
        s += v.x + v.y; sq += v.x * v.x + v.y * v.y;
    }
#pragma unroll
    for (int o = 16; o; o >>= 1) {
        s  += __shfl_xor_sync(0xffffffffu, s, o);
        sq += __shfl_xor_sync(0xffffffffu, sq, o);
    }
    float m = s * (1.f / DM);
    float var = sq * (1.f / DM) - m * m;
    float r = rsqrtf(var + 1e-5f);
    const float2* gp = reinterpret_cast<const float2*>(g);
    const float2* bp = reinterpret_cast<const float2*>(bta);
    float2* op = reinterpret_cast<float2*>(out + (size_t)row * DM);
#pragma unroll
    for (int i = 0; i < 8; i++) {
        int j = lane + i * 32;
        float2 gv = gp[j], bv = bp[j];
        float o0 = (vals[i].x - m) * r * gv.x + bv.x;
        float o1 = (vals[i].y - m) * r * gv.y + bv.y;
        op[j] = make_float2(o0, o1);
        if (out_s) {
            uint32_t hi, lo;
            split2(o0, o1, hi, lo);
            size_t o = (size_t)row * DM + ((j >> 4) * 32) + (j & 15);
            out_s[o] = hi; out_s[o + 16] = lo;
        }
    }
}

__global__ void out_kernel(const float* __restrict__ dec,
                           const float* __restrict__ means,
                           const float* __restrict__ stds,
                           float* __restrict__ out)
{
    int idx = blockIdx.x * blockDim.x + threadIdx.x;
    if (idx >= BATCH * PRED * NVARS) return;
    int b = idx / (PRED * NVARS);
    int rem = idx - b * (PRED * NVARS);
    int p = rem / NVARS;
    int n = rem - p * NVARS;
    float v = dec[((size_t)b * LTOK + n) * PRED + p];
    out[idx] = v * stds[b * NVARS + n] + means[b * NVARS + n];
}

// ================= host orchestration ======================================
template <int ACT, int OUT>
static void launch_mma(const uint32_t* A, int ldaw, const uint32_t* W,
                       const float* bias, float* C, int ldc, uint32_t* Cs,
                       int M, int N, int K,
                       const float* e1 = nullptr, const float* e2 = nullptr,
                       uint32_t* Cs2 = nullptr,
                       int Z = 1, size_t zsA = 0, size_t zsW = 0,
                       size_t zsC = 0, size_t zsBias = 0)
{
    dim3 grid(CDIV(N, BN), CDIV(M, BM), Z);
    mma_gemm<ACT, OUT><<<grid, 256, SMEM_GEMM>>>(A, ldaw, W, bias, C, ldc, Cs,
                                                 M, N, K, e1, e2, Cs2,
                                                 zsA, zsW, zsC, zsBias);
}

extern "C" void kernel_launch(void* const* d_in, const int* in_sizes, int n_in,
                              void* d_out, int out_size)
{
    const float* x_enc    = (const float*)d_in[0];
    const float* x_mark   = (const float*)d_in[1];
    const float* emb_w    = (const float*)d_in[4];
    const float* emb_b    = (const float*)d_in[5];
    const float* in_proj  = (const float*)d_in[6];
    const float* conv_w   = (const float*)d_in[7];
    const float* conv_b   = (const float*)d_in[8];
    const float* x_proj   = (const float*)d_in[9];
    const float* dt_w     = (const float*)d_in[10];
    const float* dt_b     = (const float*)d_in[11];
    const float* A_log    = (const float*)d_in[12];
    const float* D_param  = (const float*)d_in[13];
    const float* out_w    = (const float*)d_in[14];
    const float* ffn_w1   = (const float*)d_in[15];
    const float* ffn_b1   = (const float*)d_in[16];
    const float* ffn_w2   = (const float*)d_in[17];
    const float* ffn_b2   = (const float*)d_in[18];
    const float* ln1_g    = (const float*)d_in[19];
    const float* ln1_b    = (const float*)d_in[20];
    const float* ln2_g    = (const float*)d_in[21];
    const float* ln2_b    = (const float*)d_in[22];
    const float* fin_g    = (const float*)d_in[23];
    const float* fin_b    = (const float*)d_in[24];
    const float* gate_w   = (const float*)d_in[25];
    const float* gate_b   = (const float*)d_in[26];
    const float* proj_w   = (const float*)d_in[27];
    const float* proj_b   = (const float*)d_in[28];

    cudaFuncSetAttribute((const void*)mma_gemm<ACT_DUP, 2>,
                         cudaFuncAttributeMaxDynamicSharedMemorySize, SMEM_GEMM);
    cudaFuncSetAttribute((const void*)mma_gemm<ACT_NONE, 0>,
                         cudaFuncAttributeMaxDynamicSharedMemorySize, SMEM_GEMM);
    cudaFuncSetAttribute((const void*)mma_gemm<ACT_DELTABC, 0>,
                         cudaFuncAttributeMaxDynamicSharedMemorySize, SMEM_GEMM);
    cudaFuncSetAttribute((const void*)mma_gemm<ACT_RELU, 1>,
                         cudaFuncAttributeMaxDynamicSharedMemorySize, SMEM_GEMM);
    cudaFuncSetAttribute((const void*)mma_gemm<ACT_GATE, 1>,
                         cudaFuncAttributeMaxDynamicSharedMemorySize, SMEM_GEMM);

    float* S = nullptr;
    cudaGetSymbolAddress((void**)&S, g_scratch);
    uint32_t* U = reinterpret_cast<uint32_t*>(S);

    uint32_t* tok_s = U + OFF_TOKS;
    float* dec   = S + OFF_DEC;
    float* enc   = S + OFF_ENC;
    uint32_t* enc_s = U + OFF_ENCS;
    float* raw   = S + OFF_RAW;
    uint32_t* raw_s = U + OFF_RAWS;
    float* xzB   = S + OFF_XZB;
    uint32_t* xc_s = U + OFF_XCS;
    float* dx    = S + OFF_DX;
    float* bcb   = S + OFF_BC;
    uint32_t* yp_s = U + OFF_YPS;
    float* mo    = S + OFF_MO;
    float* t1    = S + OFF_T1;
    uint32_t* t1_s = U + OFF_T1S;
    float* t2    = S + OFF_T2;
    uint32_t* t2_s = U + OFF_T2S;
    float* t3    = S + OFF_T3;
    uint32_t* wc_s  = U + OFF_WCS;
    uint32_t* emb_ws = U + OFF_EMBS;
    uint32_t* inp_ws = U + OFF_INPS;
    uint32_t* out_ws = U + OFF_OUTS;
    uint32_t* f1_ws  = U + OFF_F1S;
    uint32_t* f2_ws  = U + OFF_F2S;
    uint32_t* g_ws   = U + OFF_GWS;
    uint32_t* p_ws   = U + OFF_PWS;
    float* means = S + OFF_MEAN;
    float* stds  = S + OFF_STD;
    float* Pbuf  = S + OFF_P;
    float* Hlbuf = S + OFF_HL;
    float* Hibuf = S + OFF_HI;

    // one-shot weight split + combined delta/BC weights
    wsplit_all<<<CDIV(N_ALL, 256), 256>>>(emb_w, emb_ws, in_proj, inp_ws,
                                          out_w, out_ws, ffn_w1, f1_ws,
                                          ffn_w2, f2_ws, gate_w, g_ws,
                                          proj_w, p_ws);
    wcomb_kernel<<<CDIV(4 * 544 * 256, 256), 256>>>(dt_w, x_proj, wc_s);

    stats_kernel<<<CDIV(BATCH * NVARS, 256), 256>>>(x_enc, means, stds);
    tok_kernel<<<CDIV(TTOK * 48, 256), 256>>>(x_enc, x_mark, means, stds, tok_s);

    // embedding GEMM -> enc (fp32+split) and raw (fp32+split)
    launch_mma<ACT_DUP, 2>(tok_s, 96, emb_ws, emb_b, enc, DM, enc_s,
                           TTOK, DM, 96, nullptr, raw, raw_s);

    for (int l = 0; l < NL; l++) {
        launch_mma<ACT_NONE, 0>(enc_s, DM, inp_ws + (size_t)l * 2048 * 512,
                                nullptr, xzB, 4 * DM, nullptr,
                                TTOK, 4 * DM, DM);
        conv_silu_kernel<<<CDIV(2 * TTOK * 256, 256), 256>>>(
            xzB, conv_w + (size_t)l * 2 * DM * 2, conv_b + (size_t)l * 2 * DM,
            xc_s, dx);

        launch_mma<ACT_DELTABC, 0>(xc_s, DM, wc_s + (size_t)l * 2 * 544 * 512,
                                   dt_b + (size_t)l * 2 * DM, dx, 2048, nullptr,
                                   TTOK, 544, DM, bcb, nullptr, nullptr,
                                   2, (size_t)TTOK * DM, (size_t)544 * 512,
                                   1024, DM);

        scan_p1<<<NWARP / 8, 256>>>(dx, bcb,
                                    A_log + (size_t)l * 2 * DM * DS,
                                    Pbuf, Hlbuf);
        scan_comb<<<CDIV(2 * BATCH * DM * 16, 256), 256>>>(Pbuf, Hlbuf, Hibuf);
        scan_p2<<<NWARP / 8, 256>>>(dx, bcb, xzB,
                                    A_log + (size_t)l * 2 * DM * DS,
                                    D_param + (size_t)l * 2 * DM,
                                    Hibuf, yp_s);

        launch_mma<ACT_NONE, 0>(yp_s, DM, out_ws + (size_t)l * 2 * 512 * 512,
                                nullptr, mo, DM, nullptr,
                                TTOK, DM, DM, nullptr, nullptr, nullptr,
                                2, (size_t)TTOK * DM, (size_t)512 * 512,
                                (size_t)TTOK * DM, 0);

        ln_kernel<<<CDIV(TTOK, 8), 256>>>(enc, mo, mo + (size_t)TTOK * DM,
                                          ln1_g + l * DM, ln1_b + l * DM,
                                          t1, t1_s);
        launch_mma<ACT_RELU, 1>(t1_s, DM, f1_ws + (size_t)l * 512 * 512,
                                ffn_b1 + l * DFF, nullptr, DFF, t2_s,
                                TTOK, DFF, DM);
        launch_mma<ACT_NONE, 0>(t2_s, DFF, f2_ws + (size_t)l * 512 * 512,
                                ffn_b2 + l * DM, t3, DM, nullptr,
                                TTOK, DM, DFF);
        ln_kernel<<<CDIV(TTOK, 8), 256>>>(t1, t3, nullptr,
                                          ln2_g + l * DM, ln2_b + l * DM,
                                          enc, enc_s);
    }

    ln_kernel<<<CDIV(TTOK, 8), 256>>>(enc, nullptr, nullptr, fin_g, fin_b,
                                      t2, nullptr);
    launch_mma<ACT_GATE, 1>(raw_s, DM, g_ws, gate_b, nullptr, DM, t1_s,
                            TTOK, DM, DM, t2, raw);
    launch_mma<ACT_NONE, 0>(t1_s, DM, p_ws, proj_b, dec, PRED, nullptr,
                            TTOK, PRED, DM);
    out_kernel<<<CDIV(BATCH * PRED * NVARS, 256), 256>>>(dec, means, stds,
                                                         (float*)d_out);
}

// round 9
// speedup vs baseline: 1.2531x; 1.2228x over previous
#include <cuda_runtime.h>
#include <cuda_bf16.h>
#include <cuda_fp16.h>
#include <math.h>
#include <stdint.h>

// ---------------- problem constants ----------------
#define BATCH 8
#define SEQ   96
#define PRED  96
#define NVARS 862
#define NMARK 4
#define LTOK  866
#define TTOK  (BATCH*LTOK)   // 6928
#define DM    512
#define DS    16
#define DFF   512
#define RK    32
#define NL    2

// chunked scan: warp = 32 d-channels, 16 states/lane in registers
#define NCH   32
#define CHL   28
#define NWARP (2*BATCH*16*NCH)
#define NSTATE ((size_t)NWARP*32*16)

#define CDIV(a,b) (((a)+(b)-1)/(b))

// ================= scratch (static; no allocs) =============================
constexpr size_t OFF_TOK  = 0;
constexpr size_t OFF_DEC  = OFF_TOK  + (size_t)TTOK*96;
constexpr size_t OFF_ENC  = OFF_DEC  + (size_t)TTOK*96;
constexpr size_t OFF_RAW  = OFF_ENC  + (size_t)TTOK*DM;
constexpr size_t OFF_XZB  = OFF_RAW  + (size_t)TTOK*DM;        // [T, 2048]
constexpr size_t OFF_XC0  = OFF_XZB  + (size_t)TTOK*4*DM;
constexpr size_t OFF_XC1  = OFF_XC0  + (size_t)TTOK*DM;
constexpr size_t OFF_DX   = OFF_XC1  + (size_t)TTOK*DM;        // [T,2048] (dlt,x)
constexpr size_t OFF_BC   = OFF_DX   + (size_t)TTOK*2048;      // [T,64] (B,C)
constexpr size_t OFF_YP0  = OFF_BC   + (size_t)TTOK*64;
constexpr size_t OFF_YP1  = OFF_YP0  + (size_t)TTOK*DM;
constexpr size_t OFF_MO0  = OFF_YP1  + (size_t)TTOK*DM;
constexpr size_t OFF_MO1  = OFF_MO0  + (size_t)TTOK*DM;
constexpr size_t OFF_T1   = OFF_MO1  + (size_t)TTOK*DM;
constexpr size_t OFF_T2   = OFF_T1   + (size_t)TTOK*DM;
constexpr size_t OFF_T3   = OFF_T2   + (size_t)TTOK*DM;
constexpr size_t OFF_WCOMB= OFF_T3   + (size_t)TTOK*DM;        // [4,544,512]
constexpr size_t OFF_MEAN = OFF_WCOMB+ (size_t)4*544*512;
constexpr size_t OFF_STD  = OFF_MEAN + (size_t)BATCH*NVARS;
constexpr size_t OFF_P    = OFF_STD  + (size_t)BATCH*NVARS;
constexpr size_t OFF_HL   = OFF_P    + NSTATE;
constexpr size_t OFF_HI   = OFF_HL   + NSTATE;
constexpr size_t SCRATCH_FLOATS = OFF_HI + NSTATE;

__device__ float g_scratch[SCRATCH_FLOATS];

// ================= tensor-core GEMM =========================================
// C[M,N] = act(A[M,K(lda)] * W[N,K]^T + bias)
// PREC=0: bf16 3-product split (hi*hi + lo*hi + hi*lo), ~1e-5 accuracy
// PREC=1: fp16 single product, ~2e-4 accuracy (for LN-protected GEMMs)
enum { ACT_NONE = 0, ACT_RELU = 1, ACT_DELTABC = 2, ACT_GATE = 3, ACT_DUP = 4 };

#define BM 64
#define BN 128
#define LPITCH 36                   // u32 per smem row (hi[32] lo[32] pad)
#define ROWB 144
#define A_TILE_B (64*ROWB)          // 9216
#define B_TILE_B (128*ROWB)         // 18432
#define STAGE_B  (A_TILE_B + B_TILE_B)  // 27648
#define SMEM_GEMM (2*STAGE_B)       // 55296

__device__ __forceinline__ uint32_t smem_u32(const void* p) {
    uint32_t a;
    asm("{ .reg .u64 t; cvta.to.shared.u64 t, %1; cvt.u32.u64 %0, t; }"
        : "=r"(a) : "l"(p));
    return a;
}

__device__ __forceinline__ uint32_t pack_bf16(float a, float b) {
    __nv_bfloat162 t = __floats2bfloat162_rn(a, b);
    return *reinterpret_cast<uint32_t*>(&t);
}
__device__ __forceinline__ uint32_t pack_fp16(float a, float b) {
    __half2 t = __floats2half2_rn(a, b);
    return *reinterpret_cast<uint32_t*>(&t);
}

#define LDSM_X4(r0,r1,r2,r3,addr) \
    asm volatile("ldmatrix.sync.aligned.m8n8.x4.shared.b16 {%0,%1,%2,%3}, [%4];" \
        : "=r"(r0),"=r"(r1),"=r"(r2),"=r"(r3) : "r"(addr))

#define MMA_BF16(d,a,b0,b1) \
    asm volatile("mma.sync.aligned.m16n8k16.row.col.f32.bf16.bf16.f32 " \
        "{%0,%1,%2,%3}, {%4,%5,%6,%7}, {%8,%9}, {%0,%1,%2,%3};" \
        : "+f"((d)[0]),"+f"((d)[1]),"+f"((d)[2]),"+f"((d)[3]) \
        : "r"((a)[0]),"r"((a)[1]),"r"((a)[2]),"r"((a)[3]), "r"(b0),"r"(b1))

#define MMA_FP16(d,a,b0,b1) \
    asm volatile("mma.sync.aligned.m16n8k16.row.col.f32.f16.f16.f32 " \
        "{%0,%1,%2,%3}, {%4,%5,%6,%7}, {%8,%9}, {%0,%1,%2,%3};" \
        : "+f"((d)[0]),"+f"((d)[1]),"+f"((d)[2]),"+f"((d)[3]) \
        : "r"((a)[0]),"r"((a)[1]),"r"((a)[2]),"r"((a)[3]), "r"(b0),"r"(b1))

template <int ACT, int PREC>
__global__ void __launch_bounds__(256, 2)
mma_gemm(const float* __restrict__ A, int lda,
         const float* __restrict__ W,
         const float* __restrict__ bias,
         float* __restrict__ C, int ldc,
         int M, int N, int K,
         const float* __restrict__ e1, const float* __restrict__ e2,
         size_t zsA, size_t zsW, size_t zsC, size_t zsBias)
{
    extern __shared__ char smem[];
    const uint32_t sbase = smem_u32(smem);
    const int tid  = threadIdx.x;
    const int lane = tid & 31;
    const int wid  = tid >> 5;          // 8 warps
    const int warp_m = wid & 1;         // 2 x 32 rows
    const int warp_n = wid >> 1;        // 4 x 32 cols
    const int bm = blockIdx.y * BM, bn = blockIdx.x * BN;

    A += blockIdx.z * zsA;
    W += blockIdx.z * zsW;
    C += blockIdx.z * zsC;
    if (bias) bias += blockIdx.z * zsBias;

    const int c4 = tid & 7;             // float4 index within 32-float row
    const int r0g = tid >> 3;           // base row (0..31)

    float4 aReg[2], bReg[4];

    auto load_global = [&](int kt) {
        const float* Ap = A + (size_t)kt * 32 + (size_t)c4 * 4;
        const float* Wp = W + (size_t)kt * 32 + (size_t)c4 * 4;
#pragma unroll
        for (int i = 0; i < 2; i++) {
            int gr = bm + r0g + i * 32;
            aReg[i] = (gr < M) ? *reinterpret_cast<const float4*>(Ap + (size_t)gr * lda)
                               : make_float4(0.f, 0.f, 0.f, 0.f);
        }
#pragma unroll
        for (int i = 0; i < 4; i++) {
            int gn = bn + r0g + i * 32;
            bReg[i] = (gn < N) ? *reinterpret_cast<const float4*>(Wp + (size_t)gn * K)
                               : make_float4(0.f, 0.f, 0.f, 0.f);
        }
    };

    auto store_stage = [&](int s) {
        uint32_t* sa = reinterpret_cast<uint32_t*>(smem + s * STAGE_B);
        uint32_t* sb = reinterpret_cast<uint32_t*>(smem + s * STAGE_B + A_TILE_B);
#pragma unroll
        for (int i = 0; i < 2; i++) {
            int row = r0g + i * 32;
            float4 v = aReg[i];
            uint32_t* p = sa + row * LPITCH + c4 * 2;
            if (PREC == 1) {
                p[0] = pack_fp16(v.x, v.y);
                p[1] = pack_fp16(v.z, v.w);
            } else {
                float hx = __bfloat162float(__float2bfloat16_rn(v.x));
                float hy = __bfloat162float(__float2bfloat16_rn(v.y));
                float hz = __bfloat162float(__float2bfloat16_rn(v.z));
                float hw = __bfloat162float(__float2bfloat16_rn(v.w));
                p[0] = pack_bf16(hx, hy);
                p[1] = pack_bf16(hz, hw);
                p[16] = pack_bf16(v.x - hx, v.y - hy);
                p[17] = pack_bf16(v.z - hz, v.w - hw);
            }
        }
#pragma unroll
        for (int i = 0; i < 4; i++) {
            int row = r0g + i * 32;
            float4 v = bReg[i];
            uint32_t* p = sb + row * LPITCH + c4 * 2;
            if (PREC == 1) {
                p[0] = pack_fp16(v.x, v.y);
                p[1] = pack_fp16(v.z, v.w);
            } else {
                float hx = __bfloat162float(__float2bfloat16_rn(v.x));
                float hy = __bfloat162float(__float2bfloat16_rn(v.y));
                float hz = __bfloat162float(__float2bfloat16_rn(v.z));
                float hw = __bfloat162float(__float2bfloat16_rn(v.w));
                p[0] = pack_bf16(hx, hy);
                p[1] = pack_bf16(hz, hw);
                p[16] = pack_bf16(v.x - hx, v.y - hy);
                p[17] = pack_bf16(v.z - hz, v.w - hw);
            }
        }
    };

    const uint32_t a_off = (uint32_t)(warp_m * 32 + (lane & 15)) * ROWB + ((lane >> 4) * 16);
    const uint32_t b_off = (uint32_t)(warp_n * 32 + ((lane >> 4) & 1) * 8 + (lane & 7)) * ROWB
                         + (((lane >> 3) & 1) * 16);

    float acc[2][4][4];
#pragma unroll
    for (int i = 0; i < 2; i++)
#pragma unroll
        for (int j = 0; j < 4; j++)
#pragma unroll
            for (int e = 0; e < 4; e++) acc[i][j][e] = 0.f;

    const int KT = K / 32;
    load_global(0);
    store_stage(0);
    __syncthreads();

    const int KSN = (PREC == 1) ? 2 : 6;
    for (int kt = 0; kt < KT; kt++) {
        if (kt + 1 < KT) load_global(kt + 1);
        const uint32_t Ab = sbase + (kt & 1) * STAGE_B;
        const uint32_t Bb = Ab + A_TILE_B;
        // PREC0 products: hi*hi (ks 0,1) ; lo*hi (ks 2,3) ; hi*lo (ks 4,5)
        // PREC1: single product (ks 0,1), segments always 0
#pragma unroll
        for (int ks = 0; ks < KSN; ks++) {
            const int kk = ks & 1;
            const int segA = (PREC == 0 && (ks == 2 || ks == 3)) ? 1 : 0;
            const int segB = (PREC == 0 && ks >= 4) ? 1 : 0;
            const uint32_t ao = Ab + a_off + segA * 64 + kk * 32;
            const uint32_t bo = Bb + b_off + segB * 64 + kk * 32;
            uint32_t a[2][4];
#pragma unroll
            for (int mt = 0; mt < 2; mt++)
                LDSM_X4(a[mt][0], a[mt][1], a[mt][2], a[mt][3], ao + mt * 16 * ROWB);
            uint32_t b[2][4];
#pragma unroll
            for (int p = 0; p < 2; p++)
                LDSM_X4(b[p][0], b[p][1], b[p][2], b[p][3], bo + p * 16 * ROWB);
#pragma unroll
            for (int mt = 0; mt < 2; mt++) {
                if (PREC == 1) {
                    MMA_FP16(acc[mt][0], a[mt], b[0][0], b[0][1]);
                    MMA_FP16(acc[mt][1], a[mt], b[0][2], b[0][3]);
                    MMA_FP16(acc[mt][2], a[mt], b[1][0], b[1][1]);
                    MMA_FP16(acc[mt][3], a[mt], b[1][2], b[1][3]);
                } else {
                    MMA_BF16(acc[mt][0], a[mt], b[0][0], b[0][1]);
                    MMA_BF16(acc[mt][1], a[mt], b[0][2], b[0][3]);
                    MMA_BF16(acc[mt][2], a[mt], b[1][0], b[1][1]);
                    MMA_BF16(acc[mt][3], a[mt], b[1][2], b[1][3]);
                }
            }
        }
        if (kt + 1 < KT) store_stage((kt + 1) & 1);
        __syncthreads();
    }

    // ---- epilogue ----
    const int er = bm + warp_m * 32 + (lane >> 2);
    const int ec = bn + warp_n * 32 + (lane & 3) * 2;
#pragma unroll
    for (int mt = 0; mt < 2; mt++) {
#pragma unroll
        for (int nt = 0; nt < 4; nt++) {
            int gc = ec + nt * 8;
            if (gc >= N) continue;
            float b0 = 0.f, b1 = 0.f;
            if (bias) {
                if (ACT == ACT_DELTABC) {
                    if (gc < 512)     b0 = bias[gc];
                    if (gc + 1 < 512) b1 = bias[gc + 1];
                } else {
                    b0 = bias[gc]; b1 = bias[gc + 1];
                }
            }
#pragma unroll
            for (int h = 0; h < 2; h++) {
                int gr = er + mt * 16 + h * 8;
                if (gr >= M) continue;
                float v0 = acc[mt][nt][h * 2 + 0];
                float v1 = acc[mt][nt][h * 2 + 1];
                if (ACT == ACT_NONE) {
                    v0 += b0; v1 += b1;
                    *reinterpret_cast<float2*>(&C[(size_t)gr * ldc + gc]) =
                        make_float2(v0, v1);
                } else if (ACT == ACT_DUP) {
                    v0 += b0; v1 += b1;
                    float2 o = make_float2(v0, v1);
                    size_t ix = (size_t)gr * ldc + gc;
                    *reinterpret_cast<float2*>(&C[ix]) = o;
                    *reinterpret_cast<float2*>(const_cast<float*>(&e2[ix])) = o;
                } else if (ACT == ACT_RELU) {
                    v0 = fmaxf(v0 + b0, 0.f); v1 = fmaxf(v1 + b1, 0.f);
                    *reinterpret_cast<float2*>(&C[(size_t)gr * ldc + gc]) =
                        make_float2(v0, v1);
                } else if (ACT == ACT_DELTABC) {
                    float* bco = const_cast<float*>(e1) + blockIdx.z * 32;
                    if (gc < 512) {
                        v0 += b0; v1 += b1;
                        v0 = fmaxf(v0, 0.f) + log1pf(__expf(-fabsf(v0)));
                        v1 = fmaxf(v1, 0.f) + log1pf(__expf(-fabsf(v1)));
                        C[(size_t)gr * 2048 + 2 * gc]     = v0;
                        C[(size_t)gr * 2048 + 2 * gc + 2] = v1;
                    } else if (gc < 528) {
                        int s = gc - 512;
                        bco[(size_t)gr * 64 + 2 * s]     = v0;
                        bco[(size_t)gr * 64 + 2 * s + 2] = v1;
                    } else if (gc < 544) {
                        int s = gc - 528;
                        bco[(size_t)gr * 64 + 2 * s + 1] = v0;
                        bco[(size_t)gr * 64 + 2 * s + 3] = v1;
                    }
                } else if (ACT == ACT_GATE) {
                    size_t ix = (size_t)gr * ldc + gc;
                    float s0 = 1.f / (1.f + __expf(-(v0 + b0)));
                    float s1 = 1.f / (1.f + __expf(-(v1 + b1)));
                    v0 = e1[ix] + s0 * e2[ix];
                    v1 = e1[ix + 1] + s1 * e2[ix + 1];
                    *reinterpret_cast<float2*>(&C[ix]) = make_float2(v0, v1);
                }
            }
        }
    }
}

// ================= small kernels ==========================================
__global__ void stats_kernel(const float* __restrict__ x_enc,
                             float* __restrict__ means, float* __restrict__ stds)
{
    int idx = blockIdx.x * blockDim.x + threadIdx.x;
    if (idx >= BATCH * NVARS) return;
    int b = idx / NVARS, n = idx - b * NVARS;
    float s = 0.f, sq = 0.f;
    for (int t = 0; t < SEQ; t++) {
        float v = x_enc[((size_t)b * SEQ + t) * NVARS + n];
        s += v; sq += v * v;
    }
    float m = s * (1.f / SEQ);
    float var = sq * (1.f / SEQ) - m * m;
    means[idx] = m;
    stds[idx] = sqrtf(var + 1e-5f);
}

__global__ void tok_kernel(const float* __restrict__ x_enc,
                           const float* __restrict__ x_mark,
                           const float* __restrict__ means,
                           const float* __restrict__ stds,
                           float* __restrict__ tok)
{
    int idx = blockIdx.x * blockDim.x + threadIdx.x;
    if (idx >= TTOK * SEQ) return;
    int sIdx = idx % SEQ;
    int t = idx / SEQ;
    int b = t / LTOK, v = t - b * LTOK;
    float val;
    if (v < NVARS) {
        val = (x_enc[((size_t)b * SEQ + sIdx) * NVARS + v] - means[b * NVARS + v])
              / stds[b * NVARS + v];
    } else {
        val = x_mark[((size_t)b * SEQ + sIdx) * NMARK + (v - NVARS)];
    }
    tok[idx] = val;
}

// W_comb[w][n][k]
__global__ void wcomb_kernel(const float* __restrict__ dtw,
                             const float* __restrict__ xpw,
                             float* __restrict__ wcomb)
{
    int idx = blockIdx.x * blockDim.x + threadIdx.x;
    if (idx >= 4 * 544 * 512) return;
    int w = idx / (544 * 512);
    int rem = idx - w * 544 * 512;
    int n = rem >> 9;
    int k = rem & 511;
    float v;
    if (n < 512) {
        const float* dr = dtw + ((size_t)w * 512 + n) * 32;
        const float* xr = xpw + (size_t)w * 64 * 512 + k;
        v = 0.f;
#pragma unroll
        for (int r = 0; r < 32; r++) v = fmaf(dr[r], xr[(size_t)r * 512], v);
    } else {
        v = xpw[(size_t)w * 64 * 512 + (size_t)(32 + n - 512) * 512 + k];
    }
    wcomb[idx] = v;
}

// depthwise conv(2) + SiLU, both dirs. xzB: [T,2048] = [xi0|z0|xi1|z1]
__global__ void conv_silu_kernel(const float* __restrict__ xzB,
                                 const float* __restrict__ cw,
                                 const float* __restrict__ cb,
                                 float* __restrict__ xc0, float* __restrict__ xc1,
                                 float* __restrict__ dx)
{
    int idx = blockIdx.x * blockDim.x + threadIdx.x;
    const int n = TTOK * DM;
    if (idx >= 2 * n) return;
    int dir = idx >= n;
    int r = idx - dir * n;
    int d = r & (DM - 1);
    int t = r >> 9;
    int b = t / LTOK, l = t - b * LTOK;
    const float* base = xzB + (size_t)dir * 1024;
    float cur = base[(size_t)t * 2048 + d];
    int ln = dir ? (l + 1) : (l - 1);
    float nb = 0.f;
    if (ln >= 0 && ln < LTOK)
        nb = base[(size_t)(t + (dir ? 1 : -1)) * 2048 + d];
    float w0 = cw[(size_t)dir * DM * 2 + d * 2 + 0];
    float w1 = cw[(size_t)dir * DM * 2 + d * 2 + 1];
    float v = w0 * nb + w1 * cur + cb[dir * DM + d];
    float out = v / (1.f + __expf(-v));
    (dir ? xc1 : xc0)[r] = out;
    dx[(size_t)t * 2048 + dir * 1024 + 2 * d + 1] = out;
}

// ---------------- chunked selective scan -----------------------------------
__global__ void __launch_bounds__(256)
scan_p1(const float* __restrict__ dx, const float* __restrict__ bcb,
        const float* __restrict__ A_log_l,
        float* __restrict__ P, float* __restrict__ H)
{
    int w = blockIdx.x * 8 + (threadIdx.x >> 5);
    int lane = threadIdx.x & 31;
    int ch = w & 31;
    int dblk = (w >> 5) & 15;
    int b = (w >> 9) & 7;
    int dir = w >> 12;
    int d = dblk * 32 + lane;

    float a[DS];
    bool structured = true;
#pragma unroll
    for (int s = 0; s < DS; s++) {
        a[s] = -__expf(A_log_l[((size_t)dir * DM + d) * DS + s]) * 1.44269504f;
        structured = structured &&
            (fabsf(a[s] - a[0] * (s + 1)) <= 1e-4f * fabsf(a[0] * (s + 1)));
    }

    float h[DS], Pr[DS];
#pragma unroll
    for (int s = 0; s < DS; s++) { h[s] = 0.f; Pr[s] = 1.f; }

    int i0 = ch * CHL;
    int nn = LTOK - i0; if (nn > CHL) nn = CHL; if (nn < 0) nn = 0;
    int l0 = dir ? (LTOK - 1 - i0) : i0;
    long t0 = (long)b * LTOK + l0;
    long stp = dir ? -1 : 1;
    const float2* dxp = (const float2*)dx + t0 * 1024 + dir * 512 + d;
    const float2* bp  = (const float2*)bcb + t0 * 32 + dir * 16;
    long sdx = stp * 1024, sbc = stp * 32;

    if (structured) {
        const float a0 = a[0];
        for (int i = 0; i < nn; i++) {
            float2 dv = *dxp;
            float u = dv.x * dv.y;
            float q = exp2f(dv.x * a0);
            float dA = 1.f;
#pragma unroll
            for (int s = 0; s < DS; s++) {
                dA *= q;
                float2 bcv = bp[s];
                Pr[s] *= dA;
                h[s] = fmaf(dA, h[s], bcv.x * u);
            }
            dxp += sdx; bp += sbc;
        }
    } else {
        for (int i = 0; i < nn; i++) {
            float2 dv = *dxp;
            float u = dv.x * dv.y;
#pragma unroll
            for (int s = 0; s < DS; s++) {
                float2 bcv = bp[s];
                float dA = exp2f(dv.x * a[s]);
                Pr[s] *= dA;
                h[s] = fmaf(dA, h[s], bcv.x * u);
            }
            dxp += sdx; bp += sbc;
        }
    }
    float* Po = P + ((size_t)w * 32 + lane) * 16;
    float* Ho = H + ((size_t)w * 32 + lane) * 16;
#pragma unroll
    for (int s = 0; s < DS; s++) { Po[s] = Pr[s]; Ho[s] = h[s]; }
}

__global__ void scan_comb(const float* __restrict__ P,
                          const float* __restrict__ Hl,
                          float* __restrict__ Hin)
{
    int idx = blockIdx.x * blockDim.x + threadIdx.x;
    if (idx >= 2 * BATCH * DM * 16) return;
    int s = idx & 15;
    int lane = (idx >> 4) & 31;
    int dblk = (idx >> 9) & 15;
    int b = (idx >> 13) & 7;
    int dir = idx >> 16;
    size_t w0 = (size_t)dir * 4096 + (size_t)b * 512 + (size_t)dblk * 32;
    float h = 0.f;
#pragma unroll
    for (int ch = 0; ch < NCH; ch++) {
        size_t o = ((w0 + ch) * 32 + lane) * 16 + s;
        Hin[o] = h;
        h = P[o] * h + Hl[o];
    }
}

__global__ void __launch_bounds__(256)
scan_p2(const float* __restrict__ dx, const float* __restrict__ bcb,
        const float* __restrict__ xzB,
        const float* __restrict__ A_log_l,
        const float* __restrict__ Dp_l,
        const float* __restrict__ Hin,
        float* __restrict__ yp0, float* __restrict__ yp1)
{
    int w = blockIdx.x * 8 + (threadIdx.x >> 5);
    int lane = threadIdx.x & 31;
    int ch = w & 31;
    int dblk = (w >> 5) & 15;
    int b = (w >> 9) & 7;
    int dir = w >> 12;
    int d = dblk * 32 + lane;

    float a[DS];
    bool structured = true;
#pragma unroll
    for (int s = 0; s < DS; s++) {
        a[s] = -__expf(A_log_l[((size_t)dir * DM + d) * DS + s]) * 1.44269504f;
        structured = structured &&
            (fabsf(a[s] - a[0] * (s + 1)) <= 1e-4f * fabsf(a[0] * (s + 1)));
    }
    float Dv = Dp_l[dir * DM + d];

    float h[DS];
    const float* Hi = Hin + ((size_t)w * 32 + lane) * 16;
#pragma unroll
    for (int s = 0; s < DS; s++) h[s] = Hi[s];

    int i0 = ch * CHL;
    int nn = LTOK - i0; if (nn > CHL) nn = CHL; if (nn < 0) nn = 0;
    int l0 = dir ? (LTOK - 1 - i0) : i0;
    long t0 = (long)b * LTOK + l0;
    long stp = dir ? -1 : 1;
    const float2* dxp = (const float2*)dx + t0 * 1024 + dir * 512 + d;
    const float2* bp  = (const float2*)bcb + t0 * 32 + dir * 16;
    const float*  zp  = xzB + t0 * 2048 + dir * 1024 + 512 + d;
    float* ypp = (dir ? yp1 : yp0) + t0 * 512 + d;
    long sdx = stp * 1024, sbc = stp * 32, sz = stp * 2048, sy = stp * 512;

    if (structured) {
        const float a0 = a[0];
        for (int i = 0; i < nn; i++) {
            float2 dv = *dxp;
            float u = dv.x * dv.y;
            float q = exp2f(dv.x * a0);
            float dA = 1.f;
            float y0 = 0.f, y1 = 0.f, y2 = 0.f, y3 = 0.f;
#pragma unroll
            for (int s = 0; s < DS; s++) {
                dA *= q;
                float2 bcv = bp[s];
                h[s] = fmaf(dA, h[s], bcv.x * u);
                float t = h[s] * bcv.y;
                if ((s & 3) == 0) y0 += t;
                else if ((s & 3) == 1) y1 += t;
                else if ((s & 3) == 2) y2 += t;
                else y3 += t;
            }
            float y = (y0 + y1) + (y2 + y3);
            float z = *zp;
            float szl = z / (1.f + __expf(-z));
            *ypp = (y + Dv * dv.y) * szl;
            dxp += sdx; bp += sbc; zp += sz; ypp += sy;
        }
    } else {
        for (int i = 0; i < nn; i++) {
            float2 dv = *dxp;
            float u = dv.x * dv.y;
            float y0 = 0.f, y1 = 0.f, y2 = 0.f, y3 = 0.f;
#pragma unroll
            for (int s = 0; s < DS; s++) {
                float2 bcv = bp[s];
                float dA = exp2f(dv.x * a[s]);
                h[s] = fmaf(dA, h[s], bcv.x * u);
                float t = h[s] * bcv.y;
                if ((s & 3) == 0) y0 += t;
                else if ((s & 3) == 1) y1 += t;
                else if ((s & 3) == 2) y2 += t;
                else y3 += t;
            }
            float y = (y0 + y1) + (y2 + y3);
            float z = *zp;
            float szl = z / (1.f + __expf(-z));
            *ypp = (y + Dv * dv.y) * szl;
            dxp += sdx; bp += sbc; zp += sz; ypp += sy;
        }
    }
}

__global__ void ln_kernel(const float* __restrict__ i1,
                          const float* __restrict__ i2,
                          const float* __restrict__ i3,
                          const float* __restrict__ g,
                          const float* __restrict__ bta,
                          float* __restrict__ out)
{
    int row = blockIdx.x * (blockDim.x >> 5) + (threadIdx.x >> 5);
    int lane = threadIdx.x & 31;
    if (row >= TTOK) return;
    size_t rb = (size_t)row * DM;
    float vals[16];
    float s = 0.f, sq = 0.f;
#pragma unroll
    for (int i = 0; i < 16; i++) {
        int c = lane + i * 32;
        float v = i1[rb + c];
        if (i2) v += i2[rb + c];
        if (i3) v += i3[rb + c];
        vals[i] = v; s += v; sq += v * v;
    }
#pragma unroll
    for (int o = 16; o; o >>= 1) {
        s  += __shfl_xor_sync(0xffffffffu, s, o);
        sq += __shfl_xor_sync(0xffffffffu, sq, o);
    }
    float m = s * (1.f / DM);
    float var = sq * (1.f / DM) - m * m;
    float r = rsqrtf(var + 1e-5f);
#pragma unroll
    for (int i = 0; i < 16; i++) {
        int c = lane + i * 32;
        out[rb + c] = (vals[i] - m) * r * g[c] + bta[c];
    }
}

__global__ void out_kernel(const float* __restrict__ dec,
                           const float* __restrict__ means,
                           const float* __restrict__ stds,
                           float* __restrict__ out)
{
    int idx = blockIdx.x * blockDim.x + threadIdx.x;
    if (idx >= BATCH * PRED * NVARS) return;
    int b = idx / (PRED * NVARS);
    int rem = idx - b * (PRED * NVARS);
    int p = rem / NVARS;
    int n = rem - p * NVARS;
    float v = dec[((size_t)b * LTOK + n) * PRED + p];
    out[idx] = v * stds[b * NVARS + n] + means[b * NVARS + n];
}

// ================= host orchestration ======================================
template <int ACT, int PREC>
static void launch_mma(const float* A, int lda, const float* W, const float* bias,
                       float* C, int ldc, int M, int N, int K,
                       const float* e1 = nullptr, const float* e2 = nullptr,
                       int Z = 1, size_t zsA = 0, size_t zsW = 0,
                       size_t zsC = 0, size_t zsBias = 0)
{
    dim3 grid(CDIV(N, BN), CDIV(M, BM), Z);
    mma_gemm<ACT, PREC><<<grid, 256, SMEM_GEMM>>>(A, lda, W, bias, C, ldc,
                                                  M, N, K, e1, e2,
                                                  zsA, zsW, zsC, zsBias);
}

extern "C" void kernel_launch(void* const* d_in, const int* in_sizes, int n_in,
                              void* d_out, int out_size)
{
    const float* x_enc    = (const float*)d_in[0];
    const float* x_mark   = (const float*)d_in[1];
    const float* emb_w    = (const float*)d_in[4];
    const float* emb_b    = (const float*)d_in[5];
    const float* in_proj  = (const float*)d_in[6];
    const float* conv_w   = (const float*)d_in[7];
    const float* conv_b   = (const float*)d_in[8];
    const float* x_proj   = (const float*)d_in[9];
    const float* dt_w     = (const float*)d_in[10];
    const float* dt_b     = (const float*)d_in[11];
    const float* A_log    = (const float*)d_in[12];
    const float* D_param  = (const float*)d_in[13];
    const float* out_w    = (const float*)d_in[14];
    const float* ffn_w1   = (const float*)d_in[15];
    const float* ffn_b1   = (const float*)d_in[16];
    const float* ffn_w2   = (const float*)d_in[17];
    const float* ffn_b2   = (const float*)d_in[18];
    const float* ln1_g    = (const float*)d_in[19];
    const float* ln1_b    = (const float*)d_in[20];
    const float* ln2_g    = (const float*)d_in[21];
    const float* ln2_b    = (const float*)d_in[22];
    const float* fin_g    = (const float*)d_in[23];
    const float* fin_b    = (const float*)d_in[24];
    const float* gate_w   = (const float*)d_in[25];
    const float* gate_b   = (const float*)d_in[26];
    const float* proj_w   = (const float*)d_in[27];
    const float* proj_b   = (const float*)d_in[28];

    cudaFuncSetAttribute((const void*)mma_gemm<ACT_DUP, 0>,
                         cudaFuncAttributeMaxDynamicSharedMemorySize, SMEM_GEMM);
    cudaFuncSetAttribute((const void*)mma_gemm<ACT_NONE, 1>,
                         cudaFuncAttributeMaxDynamicSharedMemorySize, SMEM_GEMM);
    cudaFuncSetAttribute((const void*)mma_gemm<ACT_DELTABC, 0>,
                         cudaFuncAttributeMaxDynamicSharedMemorySize, SMEM_GEMM);
    cudaFuncSetAttribute((const void*)mma_gemm<ACT_RELU, 1>,
                         cudaFuncAttributeMaxDynamicSharedMemorySize, SMEM_GEMM);
    cudaFuncSetAttribute((const void*)mma_gemm<ACT_GATE, 1>,
                         cudaFuncAttributeMaxDynamicSharedMemorySize, SMEM_GEMM);

    float* S = nullptr;
    cudaGetSymbolAddress((void**)&S, g_scratch);

    float* tok   = S + OFF_TOK;
    float* dec   = S + OFF_DEC;
    float* enc   = S + OFF_ENC;
    float* raw   = S + OFF_RAW;
    float* xzB   = S + OFF_XZB;
    float* xcb[2] = { S + OFF_XC0,  S + OFF_XC1 };
    float* dx    = S + OFF_DX;
    float* bcb   = S + OFF_BC;
    float* yp[2]  = { S + OFF_YP0,  S + OFF_YP1 };
    float* mo[2]  = { S + OFF_MO0,  S + OFF_MO1 };
    float* t1    = S + OFF_T1;
    float* t2    = S + OFF_T2;
    float* t3    = S + OFF_T3;
    float* wcomb = S + OFF_WCOMB;
    float* means = S + OFF_MEAN;
    float* stds  = S + OFF_STD;
    float* Pbuf  = S + OFF_P;
    float* Hlbuf = S + OFF_HL;
    float* Hibuf = S + OFF_HI;

    stats_kernel<<<CDIV(BATCH * NVARS, 256), 256>>>(x_enc, means, stds);
    tok_kernel<<<CDIV(TTOK * SEQ, 256), 256>>>(x_enc, x_mark, means, stds, tok);
    wcomb_kernel<<<CDIV(4 * 544 * 512, 256), 256>>>(dt_w, x_proj, wcomb);

    // embedding GEMM (bf16 3-prod) -> enc (+ duplicate into raw)
    launch_mma<ACT_DUP, 0>(tok, SEQ, emb_w, emb_b, enc, DM, TTOK, DM, SEQ,
                           nullptr, raw);

    for (int l = 0; l < NL; l++) {
        // merged fwd+rev in_proj: N=2048 (fp16)
        launch_mma<ACT_NONE, 1>(enc, DM, in_proj + (size_t)l * 2 * 2 * DM * DM,
                                nullptr, xzB, 4 * DM, TTOK, 4 * DM, DM);
        conv_silu_kernel<<<CDIV(2 * TTOK * DM, 256), 256>>>(
            xzB, conv_w + (size_t)l * 2 * DM * 2, conv_b + (size_t)l * 2 * DM,
            xcb[0], xcb[1], dx);

        // fused delta(softplus)+B+C GEMM, both dirs (z=2), bf16 3-prod
        launch_mma<ACT_DELTABC, 0>(xcb[0], DM, wcomb + (size_t)l * 2 * 544 * 512,
                                   dt_b + (size_t)l * 2 * DM, dx, 2048,
                                   TTOK, 544, DM, bcb, nullptr,
                                   2, (size_t)TTOK * DM, (size_t)544 * 512,
                                   1024, DM);

        // chunked scan
        scan_p1<<<NWARP / 8, 256>>>(dx, bcb,
                                    A_log + (size_t)l * 2 * DM * DS,
                                    Pbuf, Hlbuf);
        scan_comb<<<CDIV(2 * BATCH * DM * 16, 256), 256>>>(Pbuf, Hlbuf, Hibuf);
        scan_p2<<<NWARP / 8, 256>>>(dx, bcb, xzB,
                                    A_log + (size_t)l * 2 * DM * DS,
                                    D_param + (size_t)l * 2 * DM,
                                    Hibuf, yp[0], yp[1]);

        // out projection, both dirs (z=2), fp16
        launch_mma<ACT_NONE, 1>(yp[0], DM, out_w + (size_t)l * 2 * DM * DM,
                                nullptr, mo[0], DM, TTOK, DM, DM, nullptr, nullptr,
                                2, (size_t)TTOK * DM, (size_t)DM * DM,
                                (size_t)TTOK * DM, 0);

        ln_kernel<<<CDIV(TTOK, 8), 256>>>(enc, mo[0], mo[1],
                                          ln1_g + l * DM, ln1_b + l * DM, t1);
        launch_mma<ACT_RELU, 1>(t1, DM, ffn_w1 + (size_t)l * DFF * DM,
                                ffn_b1 + l * DFF, t2, DFF, TTOK, DFF, DM);
        launch_mma<ACT_NONE, 1>(t2, DFF, ffn_w2 + (size_t)l * DM * DFF,
                                ffn_b2 + l * DM, t3, DM, TTOK, DM, DFF);
        ln_kernel<<<CDIV(TTOK, 8), 256>>>(t1, t3, nullptr,
                                          ln2_g + l * DM, ln2_b + l * DM, enc);
    }

    ln_kernel<<<CDIV(TTOK, 8), 256>>>(enc, nullptr, nullptr, fin_g, fin_b, t2);
    launch_mma<ACT_GATE, 1>(raw, DM, gate_w, gate_b, t1, DM, TTOK, DM, DM,
                            t2, raw);
    launch_mma<ACT_NONE, 1>(t1, DM, proj_w, proj_b, dec, PRED, TTOK, PRED, DM);
    out_kernel<<<CDIV(BATCH * PRED * NVARS, 256), 256>>>(dec, means, stds,
                                                         (float*)d_out);
}

// round 10
// speedup vs baseline: 1.3499x; 1.0772x over previous
#include <cuda_runtime.h>
#include <cuda_bf16.h>
#include <cuda_fp16.h>
#include <math.h>
#include <stdint.h>

// ---------------- problem constants ----------------
#define BATCH 8
#define SEQ   96
#define PRED  96
#define NVARS 862
#define NMARK 4
#define LTOK  866
#define TTOK  (BATCH*LTOK)   // 6928
#define DM    512
#define DS    16
#define DFF   512
#define RK    32
#define NL    2

// chunked scan: warp = 32 d-channels, 16 states/lane in registers
#define NCH   32
#define CHL   28
#define NWARP (2*BATCH*16*NCH)
#define NSTATE ((size_t)NWARP*32*16)

#define CDIV(a,b) (((a)+(b)-1)/(b))

// ================= scratch (static; no allocs) =============================
constexpr size_t OFF_TOK  = 0;
constexpr size_t OFF_DEC  = OFF_TOK  + (size_t)TTOK*96;
constexpr size_t OFF_ENC  = OFF_DEC  + (size_t)TTOK*96;
constexpr size_t OFF_RAW  = OFF_ENC  + (size_t)TTOK*DM;
constexpr size_t OFF_XZB  = OFF_RAW  + (size_t)TTOK*DM;        // [T, 2048]
constexpr size_t OFF_XC0  = OFF_XZB  + (size_t)TTOK*4*DM;
constexpr size_t OFF_XC1  = OFF_XC0  + (size_t)TTOK*DM;
constexpr size_t OFF_DX   = OFF_XC1  + (size_t)TTOK*DM;        // [T,2048] (dlt,x)
constexpr size_t OFF_BC   = OFF_DX   + (size_t)TTOK*2048;      // [T,64] (B,C)
constexpr size_t OFF_YP0  = OFF_BC   + (size_t)TTOK*64;
constexpr size_t OFF_YP1  = OFF_YP0  + (size_t)TTOK*DM;
constexpr size_t OFF_MO0  = OFF_YP1  + (size_t)TTOK*DM;
constexpr size_t OFF_MO1  = OFF_MO0  + (size_t)TTOK*DM;
constexpr size_t OFF_T1   = OFF_MO1  + (size_t)TTOK*DM;
constexpr size_t OFF_T2   = OFF_T1   + (size_t)TTOK*DM;
constexpr size_t OFF_T3   = OFF_T2   + (size_t)TTOK*DM;
constexpr size_t OFF_WCOMB= OFF_T3   + (size_t)TTOK*DM;        // [4,544,512]
constexpr size_t OFF_MEAN = OFF_WCOMB+ (size_t)4*544*512;
constexpr size_t OFF_STD  = OFF_MEAN + (size_t)BATCH*NVARS;
constexpr size_t OFF_P    = OFF_STD  + (size_t)BATCH*NVARS;
constexpr size_t OFF_HL   = OFF_P    + NSTATE;
constexpr size_t OFF_HI   = OFF_HL   + NSTATE;
constexpr size_t SCRATCH_FLOATS = OFF_HI + NSTATE;

__device__ float g_scratch[SCRATCH_FLOATS];

// ================= tensor-core GEMM =========================================
// C[M,N] = act(A[M,K(lda)] * W[N,K]^T + bias)
// PREC=0: bf16 3-product split (hi*hi + lo*hi + hi*lo), ~1e-5 accuracy
// PREC=1: fp16 single product, ~2e-4 accuracy (LN/scan-contraction protected)
enum { ACT_NONE = 0, ACT_RELU = 1, ACT_DELTABC = 2, ACT_GATE = 3, ACT_DUP = 4 };

#define BM 64
#define BN 128
#define LPITCH 36                   // u32 per smem row (hi[32] lo[32] pad)
#define ROWB 144
#define A_TILE_B (64*ROWB)          // 9216
#define B_TILE_B (128*ROWB)         // 18432
#define STAGE_B  (A_TILE_B + B_TILE_B)  // 27648
#define SMEM_GEMM (2*STAGE_B)       // 55296

__device__ __forceinline__ uint32_t smem_u32(const void* p) {
    uint32_t a;
    asm("{ .reg .u64 t; cvta.to.shared.u64 t, %1; cvt.u32.u64 %0, t; }"
        : "=r"(a) : "l"(p));
    return a;
}

__device__ __forceinline__ uint32_t pack_bf16(float a, float b) {
    __nv_bfloat162 t = __floats2bfloat162_rn(a, b);
    return *reinterpret_cast<uint32_t*>(&t);
}
__device__ __forceinline__ uint32_t pack_fp16(float a, float b) {
    __half2 t = __floats2half2_rn(a, b);
    return *reinterpret_cast<uint32_t*>(&t);
}

#define LDSM_X4(r0,r1,r2,r3,addr) \
    asm volatile("ldmatrix.sync.aligned.m8n8.x4.shared.b16 {%0,%1,%2,%3}, [%4];" \
        : "=r"(r0),"=r"(r1),"=r"(r2),"=r"(r3) : "r"(addr))

#define MMA_BF16(d,a,b0,b1) \
    asm volatile("mma.sync.aligned.m16n8k16.row.col.f32.bf16.bf16.f32 " \
        "{%0,%1,%2,%3}, {%4,%5,%6,%7}, {%8,%9}, {%0,%1,%2,%3};" \
        : "+f"((d)[0]),"+f"((d)[1]),"+f"((d)[2]),"+f"((d)[3]) \
        : "r"((a)[0]),"r"((a)[1]),"r"((a)[2]),"r"((a)[3]), "r"(b0),"r"(b1))

#define MMA_FP16(d,a,b0,b1) \
    asm volatile("mma.sync.aligned.m16n8k16.row.col.f32.f16.f16.f32 " \
        "{%0,%1,%2,%3}, {%4,%5,%6,%7}, {%8,%9}, {%0,%1,%2,%3};" \
        : "+f"((d)[0]),"+f"((d)[1]),"+f"((d)[2]),"+f"((d)[3]) \
        : "r"((a)[0]),"r"((a)[1]),"r"((a)[2]),"r"((a)[3]), "r"(b0),"r"(b1))

template <int ACT, int PREC>
__global__ void __launch_bounds__(256, 2)
mma_gemm(const float* __restrict__ A, int lda,
         const float* __restrict__ W,
         const float* __restrict__ bias,
         float* __restrict__ C, int ldc,
         int M, int N, int K,
         const float* __restrict__ e1, const float* __restrict__ e2,
         size_t zsA, size_t zsW, size_t zsC, size_t zsBias)
{
    extern __shared__ char smem[];
    const uint32_t sbase = smem_u32(smem);
    const int tid  = threadIdx.x;
    const int lane = tid & 31;
    const int wid  = tid >> 5;          // 8 warps
    const int warp_m = wid & 1;         // 2 x 32 rows
    const int warp_n = wid >> 1;        // 4 x 32 cols
    const int bm = blockIdx.y * BM, bn = blockIdx.x * BN;

    A += blockIdx.z * zsA;
    W += blockIdx.z * zsW;
    C += blockIdx.z * zsC;
    if (bias) bias += blockIdx.z * zsBias;

    const int c4 = tid & 7;             // float4 index within 32-float row
    const int r0g = tid >> 3;           // base row (0..31)

    float4 aReg[2], bReg[4];

    auto load_global = [&](int kt) {
        const float* Ap = A + (size_t)kt * 32 + (size_t)c4 * 4;
        const float* Wp = W + (size_t)kt * 32 + (size_t)c4 * 4;
#pragma unroll
        for (int i = 0; i < 2; i++) {
            int gr = bm + r0g + i * 32;
            aReg[i] = (gr < M) ? *reinterpret_cast<const float4*>(Ap + (size_t)gr * lda)
                               : make_float4(0.f, 0.f, 0.f, 0.f);
        }
#pragma unroll
        for (int i = 0; i < 4; i++) {
            int gn = bn + r0g + i * 32;
            bReg[i] = (gn < N) ? *reinterpret_cast<const float4*>(Wp + (size_t)gn * K)
                               : make_float4(0.f, 0.f, 0.f, 0.f);
        }
    };

    auto store_stage = [&](int s) {
        uint32_t* sa = reinterpret_cast<uint32_t*>(smem + s * STAGE_B);
        uint32_t* sb = reinterpret_cast<uint32_t*>(smem + s * STAGE_B + A_TILE_B);
#pragma unroll
        for (int i = 0; i < 2; i++) {
            int row = r0g + i * 32;
            float4 v = aReg[i];
            uint32_t* p = sa + row * LPITCH + c4 * 2;
            if (PREC == 1) {
                p[0] = pack_fp16(v.x, v.y);
                p[1] = pack_fp16(v.z, v.w);
            } else {
                float hx = __bfloat162float(__float2bfloat16_rn(v.x));
                float hy = __bfloat162float(__float2bfloat16_rn(v.y));
                float hz = __bfloat162float(__float2bfloat16_rn(v.z));
                float hw = __bfloat162float(__float2bfloat16_rn(v.w));
                p[0] = pack_bf16(hx, hy);
                p[1] = pack_bf16(hz, hw);
                p[16] = pack_bf16(v.x - hx, v.y - hy);
                p[17] = pack_bf16(v.z - hz, v.w - hw);
            }
        }
#pragma unroll
        for (int i = 0; i < 4; i++) {
            int row = r0g + i * 32;
            float4 v = bReg[i];
            uint32_t* p = sb + row * LPITCH + c4 * 2;
            if (PREC == 1) {
                p[0] = pack_fp16(v.x, v.y);
                p[1] = pack_fp16(v.z, v.w);
            } else {
                float hx = __bfloat162float(__float2bfloat16_rn(v.x));
                float hy = __bfloat162float(__float2bfloat16_rn(v.y));
                float hz = __bfloat162float(__float2bfloat16_rn(v.z));
                float hw = __bfloat162float(__float2bfloat16_rn(v.w));
                p[0] = pack_bf16(hx, hy);
                p[1] = pack_bf16(hz, hw);
                p[16] = pack_bf16(v.x - hx, v.y - hy);
                p[17] = pack_bf16(v.z - hz, v.w - hw);
            }
        }
    };

    const uint32_t a_off = (uint32_t)(warp_m * 32 + (lane & 15)) * ROWB + ((lane >> 4) * 16);
    const uint32_t b_off = (uint32_t)(warp_n * 32 + ((lane >> 4) & 1) * 8 + (lane & 7)) * ROWB
                         + (((lane >> 3) & 1) * 16);

    float acc[2][4][4];
#pragma unroll
    for (int i = 0; i < 2; i++)
#pragma unroll
        for (int j = 0; j < 4; j++)
#pragma unroll
            for (int e = 0; e < 4; e++) acc[i][j][e] = 0.f;

    const int KT = K / 32;
    load_global(0);
    store_stage(0);
    __syncthreads();

    const int KSN = (PREC == 1) ? 2 : 6;
    for (int kt = 0; kt < KT; kt++) {
        if (kt + 1 < KT) load_global(kt + 1);
        const uint32_t Ab = sbase + (kt & 1) * STAGE_B;
        const uint32_t Bb = Ab + A_TILE_B;
        // PREC0 products: hi*hi (ks 0,1) ; lo*hi (ks 2,3) ; hi*lo (ks 4,5)
        // PREC1: single product (ks 0,1), segments always 0
#pragma unroll
        for (int ks = 0; ks < KSN; ks++) {
            const int kk = ks & 1;
            const int segA = (PREC == 0 && (ks == 2 || ks == 3)) ? 1 : 0;
            const int segB = (PREC == 0 && ks >= 4) ? 1 : 0;
            const uint32_t ao = Ab + a_off + segA * 64 + kk * 32;
            const uint32_t bo = Bb + b_off + segB * 64 + kk * 32;
            uint32_t a[2][4];
#pragma unroll
            for (int mt = 0; mt < 2; mt++)
                LDSM_X4(a[mt][0], a[mt][1], a[mt][2], a[mt][3], ao + mt * 16 * ROWB);
            uint32_t b[2][4];
#pragma unroll
            for (int p = 0; p < 2; p++)
                LDSM_X4(b[p][0], b[p][1], b[p][2], b[p][3], bo + p * 16 * ROWB);
#pragma unroll
            for (int mt = 0; mt < 2; mt++) {
                if (PREC == 1) {
                    MMA_FP16(acc[mt][0], a[mt], b[0][0], b[0][1]);
                    MMA_FP16(acc[mt][1], a[mt], b[0][2], b[0][3]);
                    MMA_FP16(acc[mt][2], a[mt], b[1][0], b[1][1]);
                    MMA_FP16(acc[mt][3], a[mt], b[1][2], b[1][3]);
                } else {
                    MMA_BF16(acc[mt][0], a[mt], b[0][0], b[0][1]);
                    MMA_BF16(acc[mt][1], a[mt], b[0][2], b[0][3]);
                    MMA_BF16(acc[mt][2], a[mt], b[1][0], b[1][1]);
                    MMA_BF16(acc[mt][3], a[mt], b[1][2], b[1][3]);
                }
            }
        }
        if (kt + 1 < KT) store_stage((kt + 1) & 1);
        __syncthreads();
    }

    // ---- epilogue ----
    const int er = bm + warp_m * 32 + (lane >> 2);
    const int ec = bn + warp_n * 32 + (lane & 3) * 2;
#pragma unroll
    for (int mt = 0; mt < 2; mt++) {
#pragma unroll
        for (int nt = 0; nt < 4; nt++) {
            int gc = ec + nt * 8;
            if (gc >= N) continue;
            float b0 = 0.f, b1 = 0.f;
            if (bias) {
                if (ACT == ACT_DELTABC) {
                    if (gc < 512)     b0 = bias[gc];
                    if (gc + 1 < 512) b1 = bias[gc + 1];
                } else {
                    b0 = bias[gc]; b1 = bias[gc + 1];
                }
            }
#pragma unroll
            for (int h = 0; h < 2; h++) {
                int gr = er + mt * 16 + h * 8;
                if (gr >= M) continue;
                float v0 = acc[mt][nt][h * 2 + 0];
                float v1 = acc[mt][nt][h * 2 + 1];
                if (ACT == ACT_NONE) {
                    v0 += b0; v1 += b1;
                    *reinterpret_cast<float2*>(&C[(size_t)gr * ldc + gc]) =
                        make_float2(v0, v1);
                } else if (ACT == ACT_DUP) {
                    v0 += b0; v1 += b1;
                    float2 o = make_float2(v0, v1);
                    size_t ix = (size_t)gr * ldc + gc;
                    *reinterpret_cast<float2*>(&C[ix]) = o;
                    *reinterpret_cast<float2*>(const_cast<float*>(&e2[ix])) = o;
                } else if (ACT == ACT_RELU) {
                    v0 = fmaxf(v0 + b0, 0.f); v1 = fmaxf(v1 + b1, 0.f);
                    *reinterpret_cast<float2*>(&C[(size_t)gr * ldc + gc]) =
                        make_float2(v0, v1);
                } else if (ACT == ACT_DELTABC) {
                    float* bco = const_cast<float*>(e1) + blockIdx.z * 32;
                    if (gc < 512) {
                        v0 += b0; v1 += b1;
                        v0 = fmaxf(v0, 0.f) + log1pf(__expf(-fabsf(v0)));
                        v1 = fmaxf(v1, 0.f) + log1pf(__expf(-fabsf(v1)));
                        C[(size_t)gr * 2048 + 2 * gc]     = v0;
                        C[(size_t)gr * 2048 + 2 * gc + 2] = v1;
                    } else if (gc < 528) {
                        int s = gc - 512;
                        bco[(size_t)gr * 64 + 2 * s]     = v0;
                        bco[(size_t)gr * 64 + 2 * s + 2] = v1;
                    } else if (gc < 544) {
                        int s = gc - 528;
                        bco[(size_t)gr * 64 + 2 * s + 1] = v0;
                        bco[(size_t)gr * 64 + 2 * s + 3] = v1;
                    }
                } else if (ACT == ACT_GATE) {
                    size_t ix = (size_t)gr * ldc + gc;
                    float s0 = 1.f / (1.f + __expf(-(v0 + b0)));
                    float s1 = 1.f / (1.f + __expf(-(v1 + b1)));
                    v0 = e1[ix] + s0 * e2[ix];
                    v1 = e1[ix + 1] + s1 * e2[ix + 1];
                    *reinterpret_cast<float2*>(&C[ix]) = make_float2(v0, v1);
                }
            }
        }
    }
}

// ================= small kernels ==========================================
__global__ void stats_kernel(const float* __restrict__ x_enc,
                             float* __restrict__ means, float* __restrict__ stds)
{
    int idx = blockIdx.x * blockDim.x + threadIdx.x;
    if (idx >= BATCH * NVARS) return;
    int b = idx / NVARS, n = idx - b * NVARS;
    float s = 0.f, sq = 0.f;
    for (int t = 0; t < SEQ; t++) {
        float v = x_enc[((size_t)b * SEQ + t) * NVARS + n];
        s += v; sq += v * v;
    }
    float m = s * (1.f / SEQ);
    float var = sq * (1.f / SEQ) - m * m;
    means[idx] = m;
    stds[idx] = sqrtf(var + 1e-5f);
}

__global__ void tok_kernel(const float* __restrict__ x_enc,
                           const float* __restrict__ x_mark,
                           const float* __restrict__ means,
                           const float* __restrict__ stds,
                           float* __restrict__ tok)
{
    int idx = blockIdx.x * blockDim.x + threadIdx.x;
    if (idx >= TTOK * SEQ) return;
    int sIdx = idx % SEQ;
    int t = idx / SEQ;
    int b = t / LTOK, v = t - b * LTOK;
    float val;
    if (v < NVARS) {
        val = (x_enc[((size_t)b * SEQ + sIdx) * NVARS + v] - means[b * NVARS + v])
              / stds[b * NVARS + v];
    } else {
        val = x_mark[((size_t)b * SEQ + sIdx) * NMARK + (v - NVARS)];
    }
    tok[idx] = val;
}

// W_comb[w][n][k]
__global__ void wcomb_kernel(const float* __restrict__ dtw,
                             const float* __restrict__ xpw,
                             float* __restrict__ wcomb)
{
    int idx = blockIdx.x * blockDim.x + threadIdx.x;
    if (idx >= 4 * 544 * 512) return;
    int w = idx / (544 * 512);
    int rem = idx - w * 544 * 512;
    int n = rem >> 9;
    int k = rem & 511;
    float v;
    if (n < 512) {
        const float* dr = dtw + ((size_t)w * 512 + n) * 32;
        const float* xr = xpw + (size_t)w * 64 * 512 + k;
        v = 0.f;
#pragma unroll
        for (int r = 0; r < 32; r++) v = fmaf(dr[r], xr[(size_t)r * 512], v);
    } else {
        v = xpw[(size_t)w * 64 * 512 + (size_t)(32 + n - 512) * 512 + k];
    }
    wcomb[idx] = v;
}

// depthwise conv(2) + SiLU, both dirs. xzB: [T,2048] = [xi0|z0|xi1|z1]
__global__ void conv_silu_kernel(const float* __restrict__ xzB,
                                 const float* __restrict__ cw,
                                 const float* __restrict__ cb,
                                 float* __restrict__ xc0, float* __restrict__ xc1,
                                 float* __restrict__ dx)
{
    int idx = blockIdx.x * blockDim.x + threadIdx.x;
    const int n = TTOK * DM;
    if (idx >= 2 * n) return;
    int dir = idx >= n;
    int r = idx - dir * n;
    int d = r & (DM - 1);
    int t = r >> 9;
    int b = t / LTOK, l = t - b * LTOK;
    const float* base = xzB + (size_t)dir * 1024;
    float cur = base[(size_t)t * 2048 + d];
    int ln = dir ? (l + 1) : (l - 1);
    float nb = 0.f;
    if (ln >= 0 && ln < LTOK)
        nb = base[(size_t)(t + (dir ? 1 : -1)) * 2048 + d];
    float w0 = cw[(size_t)dir * DM * 2 + d * 2 + 0];
    float w1 = cw[(size_t)dir * DM * 2 + d * 2 + 1];
    float v = w0 * nb + w1 * cur + cb[dir * DM + d];
    float out = v / (1.f + __expf(-v));
    (dir ? xc1 : xc0)[r] = out;
    dx[(size_t)t * 2048 + dir * 1024 + 2 * d + 1] = out;
}

// ---------------- chunked selective scan -----------------------------------
__global__ void __launch_bounds__(256)
scan_p1(const float* __restrict__ dx, const float* __restrict__ bcb,
        const float* __restrict__ A_log_l,
        float* __restrict__ P, float* __restrict__ H)
{
    int w = blockIdx.x * 8 + (threadIdx.x >> 5);
    int lane = threadIdx.x & 31;
    int ch = w & 31;
    int dblk = (w >> 5) & 15;
    int b = (w >> 9) & 7;
    int dir = w >> 12;
    int d = dblk * 32 + lane;

    float a[DS];
    bool structured = true;
#pragma unroll
    for (int s = 0; s < DS; s++) {
        a[s] = -__expf(A_log_l[((size_t)dir * DM + d) * DS + s]) * 1.44269504f;
        structured = structured &&
            (fabsf(a[s] - a[0] * (s + 1)) <= 1e-4f * fabsf(a[0] * (s + 1)));
    }

    float h[DS], Pr[DS];
#pragma unroll
    for (int s = 0; s < DS; s++) { h[s] = 0.f; Pr[s] = 1.f; }

    int i0 = ch * CHL;
    int nn = LTOK - i0; if (nn > CHL) nn = CHL; if (nn < 0) nn = 0;
    int l0 = dir ? (LTOK - 1 - i0) : i0;
    long t0 = (long)b * LTOK + l0;
    long stp = dir ? -1 : 1;
    const float2* dxp = (const float2*)dx + t0 * 1024 + dir * 512 + d;
    const float2* bp  = (const float2*)bcb + t0 * 32 + dir * 16;
    long sdx = stp * 1024, sbc = stp * 32;

    if (structured) {
        const float a0 = a[0];
        for (int i = 0; i < nn; i++) {
            float2 dv = *dxp;
            float u = dv.x * dv.y;
            float q = exp2f(dv.x * a0);
            float dA = 1.f;
#pragma unroll
            for (int s = 0; s < DS; s++) {
                dA *= q;
                float2 bcv = bp[s];
                Pr[s] *= dA;
                h[s] = fmaf(dA, h[s], bcv.x * u);
            }
            dxp += sdx; bp += sbc;
        }
    } else {
        for (int i = 0; i < nn; i++) {
            float2 dv = *dxp;
            float u = dv.x * dv.y;
#pragma unroll
            for (int s = 0; s < DS; s++) {
                float2 bcv = bp[s];
                float dA = exp2f(dv.x * a[s]);
                Pr[s] *= dA;
                h[s] = fmaf(dA, h[s], bcv.x * u);
            }
            dxp += sdx; bp += sbc;
        }
    }
    float* Po = P + ((size_t)w * 32 + lane) * 16;
    float* Ho = H + ((size_t)w * 32 + lane) * 16;
#pragma unroll
    for (int s = 0; s < DS; s++) { Po[s] = Pr[s]; Ho[s] = h[s]; }
}

__global__ void scan_comb(const float* __restrict__ P,
                          const float* __restrict__ Hl,
                          float* __restrict__ Hin)
{
    int idx = blockIdx.x * blockDim.x + threadIdx.x;
    if (idx >= 2 * BATCH * DM * 16) return;
    int s = idx & 15;
    int lane = (idx >> 4) & 31;
    int dblk = (idx >> 9) & 15;
    int b = (idx >> 13) & 7;
    int dir = idx >> 16;
    size_t w0 = (size_t)dir * 4096 + (size_t)b * 512 + (size_t)dblk * 32;
    float h = 0.f;
#pragma unroll
    for (int ch = 0; ch < NCH; ch++) {
        size_t o = ((w0 + ch) * 32 + lane) * 16 + s;
        Hin[o] = h;
        h = P[o] * h + Hl[o];
    }
}

__global__ void __launch_bounds__(256)
scan_p2(const float* __restrict__ dx, const float* __restrict__ bcb,
        const float* __restrict__ xzB,
        const float* __restrict__ A_log_l,
        const float* __restrict__ Dp_l,
        const float* __restrict__ Hin,
        float* __restrict__ yp0, float* __restrict__ yp1)
{
    int w = blockIdx.x * 8 + (threadIdx.x >> 5);
    int lane = threadIdx.x & 31;
    int ch = w & 31;
    int dblk = (w >> 5) & 15;
    int b = (w >> 9) & 7;
    int dir = w >> 12;
    int d = dblk * 32 + lane;

    float a[DS];
    bool structured = true;
#pragma unroll
    for (int s = 0; s < DS; s++) {
        a[s] = -__expf(A_log_l[((size_t)dir * DM + d) * DS + s]) * 1.44269504f;
        structured = structured &&
            (fabsf(a[s] - a[0] * (s + 1)) <= 1e-4f * fabsf(a[0] * (s + 1)));
    }
    float Dv = Dp_l[dir * DM + d];

    float h[DS];
    const float* Hi = Hin + ((size_t)w * 32 + lane) * 16;
#pragma unroll
    for (int s = 0; s < DS; s++) h[s] = Hi[s];

    int i0 = ch * CHL;
    int nn = LTOK - i0; if (nn > CHL) nn = CHL; if (nn < 0) nn = 0;
    int l0 = dir ? (LTOK - 1 - i0) : i0;
    long t0 = (long)b * LTOK + l0;
    long stp = dir ? -1 : 1;
    const float2* dxp = (const float2*)dx + t0 * 1024 + dir * 512 + d;
    const float2* bp  = (const float2*)bcb + t0 * 32 + dir * 16;
    const float*  zp  = xzB + t0 * 2048 + dir * 1024 + 512 + d;
    float* ypp = (dir ? yp1 : yp0) + t0 * 512 + d;
    long sdx = stp * 1024, sbc = stp * 32, sz = stp * 2048, sy = stp * 512;

    if (structured) {
        const float a0 = a[0];
        for (int i = 0; i < nn; i++) {
            float2 dv = *dxp;
            float u = dv.x * dv.y;
            float q = exp2f(dv.x * a0);
            float dA = 1.f;
            float y0 = 0.f, y1 = 0.f, y2 = 0.f, y3 = 0.f;
#pragma unroll
            for (int s = 0; s < DS; s++) {
                dA *= q;
                float2 bcv = bp[s];
                h[s] = fmaf(dA, h[s], bcv.x * u);
                float t = h[s] * bcv.y;
                if ((s & 3) == 0) y0 += t;
                else if ((s & 3) == 1) y1 += t;
                else if ((s & 3) == 2) y2 += t;
                else y3 += t;
            }
            float y = (y0 + y1) + (y2 + y3);
            float z = *zp;
            float szl = z / (1.f + __expf(-z));
            *ypp = (y + Dv * dv.y) * szl;
            dxp += sdx; bp += sbc; zp += sz; ypp += sy;
        }
    } else {
        for (int i = 0; i < nn; i++) {
            float2 dv = *dxp;
            float u = dv.x * dv.y;
            float y0 = 0.f, y1 = 0.f, y2 = 0.f, y3 = 0.f;
#pragma unroll
            for (int s = 0; s < DS; s++) {
                float2 bcv = bp[s];
                float dA = exp2f(dv.x * a[s]);
                h[s] = fmaf(dA, h[s], bcv.x * u);
                float t = h[s] * bcv.y;
                if ((s & 3) == 0) y0 += t;
                else if ((s & 3) == 1) y1 += t;
                else if ((s & 3) == 2) y2 += t;
                else y3 += t;
            }
            float y = (y0 + y1) + (y2 + y3);
            float z = *zp;
            float szl = z / (1.f + __expf(-z));
            *ypp = (y + Dv * dv.y) * szl;
            dxp += sdx; bp += sbc; zp += sz; ypp += sy;
        }
    }
}

// LayerNorm, float2 lanes
__global__ void ln_kernel(const float* __restrict__ i1,
                          const float* __restrict__ i2,
                          const float* __restrict__ i3,
                          const float* __restrict__ g,
                          const float* __restrict__ bta,
                          float* __restrict__ out)
{
    int row = blockIdx.x * (blockDim.x >> 5) + (threadIdx.x >> 5);
    int lane = threadIdx.x & 31;
    if (row >= TTOK) return;
    const float2* p1 = reinterpret_cast<const float2*>(i1 + (size_t)row * DM);
    const float2* p2 = i2 ? reinterpret_cast<const float2*>(i2 + (size_t)row * DM) : nullptr;
    const float2* p3 = i3 ? reinterpret_cast<const float2*>(i3 + (size_t)row * DM) : nullptr;
    float2 vals[8];
    float s = 0.f, sq = 0.f;
#pragma unroll
    for (int i = 0; i < 8; i++) {
        int j = lane + i * 32;
        float2 v = p1[j];
        if (p2) { float2 w = p2[j]; v.x += w.x; v.y += w.y; }
        if (p3) { float2 w = p3[j]; v.x += w.x; v.y += w.y; }
        vals[i] = v;
        s += v.x + v.y; sq += v.x * v.x + v.y * v.y;
    }
#pragma unroll
    for (int o = 16; o; o >>= 1) {
        s  += __shfl_xor_sync(0xffffffffu, s, o);
        sq += __shfl_xor_sync(0xffffffffu, sq, o);
    }
    float m = s * (1.f / DM);
    float var = sq * (1.f / DM) - m * m;
    float r = rsqrtf(var + 1e-5f);
    const float2* gp = reinterpret_cast<const float2*>(g);
    const float2* bp = reinterpret_cast<const float2*>(bta);
    float2* op = reinterpret_cast<float2*>(out + (size_t)row * DM);
#pragma unroll
    for (int i = 0; i < 8; i++) {
        int j = lane + i * 32;
        float2 gv = gp[j], bv = bp[j];
        op[j] = make_float2((vals[i].x - m) * r * gv.x + bv.x,
                            (vals[i].y - m) * r * gv.y + bv.y);
    }
}

__global__ void out_kernel(const float* __restrict__ dec,
                           const float* __restrict__ means,
                           const float* __restrict__ stds,
                           float* __restrict__ out)
{
    int idx = blockIdx.x * blockDim.x + threadIdx.x;
    if (idx >= BATCH * PRED * NVARS) return;
    int b = idx / (PRED * NVARS);
    int rem = idx - b * (PRED * NVARS);
    int p = rem / NVARS;
    int n = rem - p * NVARS;
    float v = dec[((size_t)b * LTOK + n) * PRED + p];
    out[idx] = v * stds[b * NVARS + n] + means[b * NVARS + n];
}

// ================= host orchestration ======================================
template <int ACT, int PREC>
static void launch_mma(const float* A, int lda, const float* W, const float* bias,
                       float* C, int ldc, int M, int N, int K,
                       const float* e1 = nullptr, const float* e2 = nullptr,
                       int Z = 1, size_t zsA = 0, size_t zsW = 0,
                       size_t zsC = 0, size_t zsBias = 0)
{
    dim3 grid(CDIV(N, BN), CDIV(M, BM), Z);
    mma_gemm<ACT, PREC><<<grid, 256, SMEM_GEMM>>>(A, lda, W, bias, C, ldc,
                                                  M, N, K, e1, e2,
                                                  zsA, zsW, zsC, zsBias);
}

extern "C" void kernel_launch(void* const* d_in, const int* in_sizes, int n_in,
                              void* d_out, int out_size)
{
    const float* x_enc    = (const float*)d_in[0];
    const float* x_mark   = (const float*)d_in[1];
    const float* emb_w    = (const float*)d_in[4];
    const float* emb_b    = (const float*)d_in[5];
    const float* in_proj  = (const float*)d_in[6];
    const float* conv_w   = (const float*)d_in[7];
    const float* conv_b   = (const float*)d_in[8];
    const float* x_proj   = (const float*)d_in[9];
    const float* dt_w     = (const float*)d_in[10];
    const float* dt_b     = (const float*)d_in[11];
    const float* A_log    = (const float*)d_in[12];
    const float* D_param  = (const float*)d_in[13];
    const float* out_w    = (const float*)d_in[14];
    const float* ffn_w1   = (const float*)d_in[15];
    const float* ffn_b1   = (const float*)d_in[16];
    const float* ffn_w2   = (const float*)d_in[17];
    const float* ffn_b2   = (const float*)d_in[18];
    const float* ln1_g    = (const float*)d_in[19];
    const float* ln1_b    = (const float*)d_in[20];
    const float* ln2_g    = (const float*)d_in[21];
    const float* ln2_b    = (const float*)d_in[22];
    const float* fin_g    = (const float*)d_in[23];
    const float* fin_b    = (const float*)d_in[24];
    const float* gate_w   = (const float*)d_in[25];
    const float* gate_b   = (const float*)d_in[26];
    const float* proj_w   = (const float*)d_in[27];
    const float* proj_b   = (const float*)d_in[28];

    cudaFuncSetAttribute((const void*)mma_gemm<ACT_DUP, 0>,
                         cudaFuncAttributeMaxDynamicSharedMemorySize, SMEM_GEMM);
    cudaFuncSetAttribute((const void*)mma_gemm<ACT_NONE, 1>,
                         cudaFuncAttributeMaxDynamicSharedMemorySize, SMEM_GEMM);
    cudaFuncSetAttribute((const void*)mma_gemm<ACT_DELTABC, 1>,
                         cudaFuncAttributeMaxDynamicSharedMemorySize, SMEM_GEMM);
    cudaFuncSetAttribute((const void*)mma_gemm<ACT_RELU, 1>,
                         cudaFuncAttributeMaxDynamicSharedMemorySize, SMEM_GEMM);
    cudaFuncSetAttribute((const void*)mma_gemm<ACT_GATE, 1>,
                         cudaFuncAttributeMaxDynamicSharedMemorySize, SMEM_GEMM);

    float* S = nullptr;
    cudaGetSymbolAddress((void**)&S, g_scratch);

    float* tok   = S + OFF_TOK;
    float* dec   = S + OFF_DEC;
    float* enc   = S + OFF_ENC;
    float* raw   = S + OFF_RAW;
    float* xzB   = S + OFF_XZB;
    float* xcb[2] = { S + OFF_XC0,  S + OFF_XC1 };
    float* dx    = S + OFF_DX;
    float* bcb   = S + OFF_BC;
    float* yp[2]  = { S + OFF_YP0,  S + OFF_YP1 };
    float* mo[2]  = { S + OFF_MO0,  S + OFF_MO1 };
    float* t1    = S + OFF_T1;
    float* t2    = S + OFF_T2;
    float* t3    = S + OFF_T3;
    float* wcomb = S + OFF_WCOMB;
    float* means = S + OFF_MEAN;
    float* stds  = S + OFF_STD;
    float* Pbuf  = S + OFF_P;
    float* Hlbuf = S + OFF_HL;
    float* Hibuf = S + OFF_HI;

    stats_kernel<<<CDIV(BATCH * NVARS, 256), 256>>>(x_enc, means, stds);
    tok_kernel<<<CDIV(TTOK * SEQ, 256), 256>>>(x_enc, x_mark, means, stds, tok);
    wcomb_kernel<<<CDIV(4 * 544 * 512, 256), 256>>>(dt_w, x_proj, wcomb);

    // embedding GEMM (bf16 3-prod) -> enc (+ duplicate into raw)
    launch_mma<ACT_DUP, 0>(tok, SEQ, emb_w, emb_b, enc, DM, TTOK, DM, SEQ,
                           nullptr, raw);

    for (int l = 0; l < NL; l++) {
        // merged fwd+rev in_proj: N=2048 (fp16)
        launch_mma<ACT_NONE, 1>(enc, DM, in_proj + (size_t)l * 2 * 2 * DM * DM,
                                nullptr, xzB, 4 * DM, TTOK, 4 * DM, DM);
        conv_silu_kernel<<<CDIV(2 * TTOK * DM, 256), 256>>>(
            xzB, conv_w + (size_t)l * 2 * DM * 2, conv_b + (size_t)l * 2 * DM,
            xcb[0], xcb[1], dx);

        // fused delta(softplus)+B+C GEMM, both dirs (z=2), fp16
        launch_mma<ACT_DELTABC, 1>(xcb[0], DM, wcomb + (size_t)l * 2 * 544 * 512,
                                   dt_b + (size_t)l * 2 * DM, dx, 2048,
                                   TTOK, 544, DM, bcb, nullptr,
                                   2, (size_t)TTOK * DM, (size_t)544 * 512,
                                   1024, DM);

        // chunked scan
        scan_p1<<<NWARP / 8, 256>>>(dx, bcb,
                                    A_log + (size_t)l * 2 * DM * DS,
                                    Pbuf, Hlbuf);
        scan_comb<<<CDIV(2 * BATCH * DM * 16, 256), 256>>>(Pbuf, Hlbuf, Hibuf);
        scan_p2<<<NWARP / 8, 256>>>(dx, bcb, xzB,
                                    A_log + (size_t)l * 2 * DM * DS,
                                    D_param + (size_t)l * 2 * DM,
                                    Hibuf, yp[0], yp[1]);

        // out projection, both dirs (z=2), fp16
        launch_mma<ACT_NONE, 1>(yp[0], DM, out_w + (size_t)l * 2 * DM * DM,
                                nullptr, mo[0], DM, TTOK, DM, DM, nullptr, nullptr,
                                2, (size_t)TTOK * DM, (size_t)DM * DM,
                                (size_t)TTOK * DM, 0);

        ln_kernel<<<CDIV(TTOK, 8), 256>>>(enc, mo[0], mo[1],
                                          ln1_g + l * DM, ln1_b + l * DM, t1);
        launch_mma<ACT_RELU, 1>(t1, DM, ffn_w1 + (size_t)l * DFF * DM,
                                ffn_b1 + l * DFF, t2, DFF, TTOK, DFF, DM);
        launch_mma<ACT_NONE, 1>(t2, DFF, ffn_w2 + (size_t)l * DM * DFF,
                                ffn_b2 + l * DM, t3, DM, TTOK, DM, DFF);
        ln_kernel<<<CDIV(TTOK, 8), 256>>>(t1, t3, nullptr,
                                          ln2_g + l * DM, ln2_b + l * DM, enc);
    }

    ln_kernel<<<CDIV(TTOK, 8), 256>>>(enc, nullptr, nullptr, fin_g, fin_b, t2);
    launch_mma<ACT_GATE, 1>(raw, DM, gate_w, gate_b, t1, DM, TTOK, DM, DM,
                            t2, raw);
    launch_mma<ACT_NONE, 1>(t1, DM, proj_w, proj_b, dec, PRED, TTOK, PRED, DM);
    out_kernel<<<CDIV(BATCH * PRED * NVARS, 256), 256>>>(dec, means, stds,
                                                         (float*)d_out);
}